// round 2
// baseline (speedup 1.0000x reference)
#include <cuda_runtime.h>
#include <math.h>

#define N_NODES 20000
#define N_EDGES 320000
#define H 128
#define NRBF 20
#define NATTR 28
#define F48 48            // NATTR + NRBF
#define TILE_E 64
#define NTILES (N_EDGES / TILE_E)   // 5000 exactly

typedef unsigned long long u64t;

// ---------------- packed f32x2 helpers (SASS FFMA2 path) ----------------
__device__ __forceinline__ u64t f2pack(float a, float b) {
    u64t r; asm("mov.b64 %0,{%1,%2};" : "=l"(r) : "f"(a), "f"(b)); return r;
}
__device__ __forceinline__ u64t f2bcast(float a) { return f2pack(a, a); }
__device__ __forceinline__ u64t f2fma(u64t a, u64t b, u64t c) {
    u64t d; asm("fma.rn.f32x2 %0,%1,%2,%3;" : "=l"(d) : "l"(a), "l"(b), "l"(c)); return d;
}
__device__ __forceinline__ u64t f2add(u64t a, u64t b) {
    u64t d; asm("add.rn.f32x2 %0,%1,%2;" : "=l"(d) : "l"(a), "l"(b)); return d;
}
__device__ __forceinline__ float2 f2unpack(u64t v) {
    float2 r; asm("mov.b64 {%0,%1},%2;" : "=f"(r.x), "=f"(r.y) : "l"(v)); return r;
}
__device__ __forceinline__ u64t f2relu(u64t v) {
    float2 t = f2unpack(v);
    return f2pack(fmaxf(t.x, 0.f), fmaxf(t.y, 0.f));
}

// ---------------- device scratch (no dynamic alloc allowed) ----------------
__device__ float g_P[N_NODES * H];     // h @ ew1[48:176] + eb1   (dst part)
__device__ float g_Q[N_NODES * H];     // h @ ew1[176:304]        (src part)
__device__ float g_mi[N_NODES * H];    // segment_sum(mij*eij)
__device__ float g_xacc[N_NODES * 3];  // segment_sum(rel_x*xg)

// =====================================================================
// Kernel 1: P/Q node pre-GEMMs + zero the accumulators
// =====================================================================
__global__ __launch_bounds__(256) void k_pre(
    const float* __restrict__ h,
    const float* __restrict__ ew1,
    const float* __restrict__ eb1)
{
    for (int i = blockIdx.x * 256 + threadIdx.x; i < N_NODES * H; i += gridDim.x * 256)
        g_mi[i] = 0.f;
    for (int i = blockIdx.x * 256 + threadIdx.x; i < N_NODES * 3; i += gridDim.x * 256)
        g_xacc[i] = 0.f;

    __shared__ float hs[32 * 128];
    __shared__ float ws[32 * 128];

    const int tid = threadIdx.x;
    const int n0  = blockIdx.x * 32;
    const int tx  = tid & 15;
    const int ny  = tid >> 4;

    for (int i = tid; i < 32 * 128 / 4; i += 256)
        ((float4*)hs)[i] = ((const float4*)(h + (size_t)n0 * H))[i];

    for (int part = 0; part < 2; part++) {
        u64t acc[2][4];
        if (part == 0) {
            const u64t* bp = (const u64t*)(eb1 + tx * 8);
            u64t b0 = bp[0], b1 = bp[1], b2 = bp[2], b3 = bp[3];
            acc[0][0] = b0; acc[0][1] = b1; acc[0][2] = b2; acc[0][3] = b3;
            acc[1][0] = b0; acc[1][1] = b1; acc[1][2] = b2; acc[1][3] = b3;
        } else {
            #pragma unroll
            for (int i = 0; i < 2; i++)
                #pragma unroll
                for (int j = 0; j < 4; j++) acc[i][j] = 0ull;
        }

        const int roff = (part == 0) ? 48 : 176;
        for (int kt = 0; kt < 128; kt += 32) {
            __syncthreads();
            for (int i = tid; i < 32 * 128 / 4; i += 256)
                ((float4*)ws)[i] = ((const float4*)(ew1 + (size_t)(roff + kt) * H))[i];
            __syncthreads();
            #pragma unroll 4
            for (int kk = 0; kk < 32; kk++) {
                u64t b0 = f2bcast(hs[(2 * ny + 0) * 128 + kt + kk]);
                u64t b1 = f2bcast(hs[(2 * ny + 1) * 128 + kt + kk]);
                ulonglong2 wa = *(const ulonglong2*)&ws[kk * 128 + tx * 8];
                ulonglong2 wb = *(const ulonglong2*)&ws[kk * 128 + tx * 8 + 4];
                acc[0][0] = f2fma(wa.x, b0, acc[0][0]);
                acc[0][1] = f2fma(wa.y, b0, acc[0][1]);
                acc[0][2] = f2fma(wb.x, b0, acc[0][2]);
                acc[0][3] = f2fma(wb.y, b0, acc[0][3]);
                acc[1][0] = f2fma(wa.x, b1, acc[1][0]);
                acc[1][1] = f2fma(wa.y, b1, acc[1][1]);
                acc[1][2] = f2fma(wb.x, b1, acc[1][2]);
                acc[1][3] = f2fma(wb.y, b1, acc[1][3]);
            }
        }
        float* dst = (part == 0) ? g_P : g_Q;
        #pragma unroll
        for (int i = 0; i < 2; i++) {
            ulonglong2* op = (ulonglong2*)&dst[(size_t)(n0 + 2 * ny + i) * H + tx * 8];
            op[0] = make_ulonglong2(acc[i][0], acc[i][1]);
            op[1] = make_ulonglong2(acc[i][2], acc[i][3]);
        }
        __syncthreads();
    }
}

// =====================================================================
// Kernel 2: fused edge kernel (persistent), FFMA2 inner loops
// =====================================================================
__global__ __launch_bounds__(256, 1) void k_edge(
    const float* __restrict__ x,
    const float* __restrict__ edge_attr,
    const float* __restrict__ ew1,
    const float* __restrict__ ew2,
    const float* __restrict__ eb2,
    const float* __restrict__ inf_w,
    const float* __restrict__ inf_b,
    const float* __restrict__ xw1,
    const float* __restrict__ xb1,
    const float* __restrict__ xw2,
    const float* __restrict__ xb2,
    const int* __restrict__ ei)
{
    extern __shared__ float sm[];
    float* ew1s  = sm;                    // 48*128  = 6144
    float* ew2s  = ew1s + 48 * 128;       // 128*128 = 16384
    float* xw1s  = ew2s + 128 * 128;      // 16384
    float* us    = xw1s + 128 * 128;      // 64*132  = 8448
    float* ms    = us + 64 * 132;         // 8448  (f48 aliased inside)
    float* f48s  = ms;                    // 64*49 = 3136 (dead before ms written)
    float* eb2s  = ms + 64 * 132;         // 128
    float* xb1s  = eb2s + 128;            // 128
    float* infws = xb1s + 128;            // 128
    float* xw2s  = infws + 128;           // 128
    float* eijs  = xw2s + 128;            // 64
    float* rels  = eijs + 64;             // 192
    int*   dsts  = (int*)(rels + 192);    // 64
    int*   srcs  = dsts + 64;             // 64

    const int tid = threadIdx.x;

    for (int i = tid; i < 48 * 128 / 4; i += 256)  ((float4*)ew1s)[i] = ((const float4*)ew1)[i];
    for (int i = tid; i < 128 * 128 / 4; i += 256) ((float4*)ew2s)[i] = ((const float4*)ew2)[i];
    for (int i = tid; i < 128 * 128 / 4; i += 256) ((float4*)xw1s)[i] = ((const float4*)xw1)[i];
    if (tid < 128) {
        eb2s[tid]  = eb2[tid];
        xb1s[tid]  = xb1[tid];
        infws[tid] = inf_w[tid];
        xw2s[tid]  = xw2[tid];
    }
    const float infb = inf_b[0];
    const float xb2v = xb2[0];

    const int tx = tid & 15;   // cols tx*8 .. tx*8+7
    const int ey = tid >> 4;   // edges ey*4 .. ey*4+3

    const float OFFSTEP = 100.f / 19.f;
    const float COEFF   = -0.5f / (OFFSTEP * OFFSTEP);

    for (int t = blockIdx.x; t < NTILES; t += gridDim.x) {
        const int e0 = t * TILE_E;
        __syncthreads();

        // ---- stage edge_attr + rbf + indices + rel_x ----
        for (int i = tid; i < TILE_E * NATTR; i += 256) {
            int e = i / NATTR, k = i - e * NATTR;
            f48s[e * 49 + k] = edge_attr[(size_t)(e0 + e) * NATTR + k];
        }
        if (tid < TILE_E) {
            int e = e0 + tid;
            int d = ei[e], s = ei[N_EDGES + e];
            dsts[tid] = d; srcs[tid] = s;
            float rx = x[d * 3 + 0] - x[s * 3 + 0];
            float ry = x[d * 3 + 1] - x[s * 3 + 1];
            float rz = x[d * 3 + 2] - x[s * 3 + 2];
            rels[tid * 3 + 0] = rx; rels[tid * 3 + 1] = ry; rels[tid * 3 + 2] = rz;
            float l2 = sqrtf(rx * rx + ry * ry + rz * rz);
            #pragma unroll
            for (int k = 0; k < NRBF; k++) {
                float dd = l2 - (float)k * OFFSTEP;
                f48s[tid * 49 + NATTR + k] = expf(COEFF * dd * dd);
            }
        }
        __syncthreads();

        // ---- GEMM1: u = relu(P[dst] + Q[src] + f48 @ ew1[0:48]) ----
        u64t acc[4][4];
        int ed[4];
        #pragma unroll
        for (int i = 0; i < 4; i++) ed[i] = dsts[ey * 4 + i];
        #pragma unroll
        for (int i = 0; i < 4; i++) {
            int s = srcs[ey * 4 + i];
            const ulonglong2* Pp = (const ulonglong2*)(g_P + (size_t)ed[i] * H + tx * 8);
            const ulonglong2* Qp = (const ulonglong2*)(g_Q + (size_t)s * H + tx * 8);
            ulonglong2 p0 = Pp[0], p1 = Pp[1];
            ulonglong2 q0 = Qp[0], q1 = Qp[1];
            acc[i][0] = f2add(p0.x, q0.x);
            acc[i][1] = f2add(p0.y, q0.y);
            acc[i][2] = f2add(p1.x, q1.x);
            acc[i][3] = f2add(p1.y, q1.y);
        }
        #pragma unroll 4
        for (int k = 0; k < F48; k++) {
            ulonglong2 wa = *(const ulonglong2*)&ew1s[k * 128 + tx * 8];
            ulonglong2 wb = *(const ulonglong2*)&ew1s[k * 128 + tx * 8 + 4];
            u64t b0 = f2bcast(f48s[(ey * 4 + 0) * 49 + k]);
            u64t b1 = f2bcast(f48s[(ey * 4 + 1) * 49 + k]);
            u64t b2 = f2bcast(f48s[(ey * 4 + 2) * 49 + k]);
            u64t b3 = f2bcast(f48s[(ey * 4 + 3) * 49 + k]);
            acc[0][0] = f2fma(wa.x, b0, acc[0][0]); acc[0][1] = f2fma(wa.y, b0, acc[0][1]);
            acc[0][2] = f2fma(wb.x, b0, acc[0][2]); acc[0][3] = f2fma(wb.y, b0, acc[0][3]);
            acc[1][0] = f2fma(wa.x, b1, acc[1][0]); acc[1][1] = f2fma(wa.y, b1, acc[1][1]);
            acc[1][2] = f2fma(wb.x, b1, acc[1][2]); acc[1][3] = f2fma(wb.y, b1, acc[1][3]);
            acc[2][0] = f2fma(wa.x, b2, acc[2][0]); acc[2][1] = f2fma(wa.y, b2, acc[2][1]);
            acc[2][2] = f2fma(wb.x, b2, acc[2][2]); acc[2][3] = f2fma(wb.y, b2, acc[2][3]);
            acc[3][0] = f2fma(wa.x, b3, acc[3][0]); acc[3][1] = f2fma(wa.y, b3, acc[3][1]);
            acc[3][2] = f2fma(wb.x, b3, acc[3][2]); acc[3][3] = f2fma(wb.y, b3, acc[3][3]);
        }
        #pragma unroll
        for (int i = 0; i < 4; i++) {
            ulonglong2* op = (ulonglong2*)&us[(ey * 4 + i) * 132 + tx * 8];
            op[0] = make_ulonglong2(f2relu(acc[i][0]), f2relu(acc[i][1]));
            op[1] = make_ulonglong2(f2relu(acc[i][2]), f2relu(acc[i][3]));
        }
        __syncthreads();

        // ---- GEMM2: mij = relu(u @ ew2 + eb2); eij ----
        {
            const ulonglong2* bp = (const ulonglong2*)&eb2s[tx * 8];
            ulonglong2 ba = bp[0], bb = bp[1];
            #pragma unroll
            for (int i = 0; i < 4; i++) {
                acc[i][0] = ba.x; acc[i][1] = ba.y; acc[i][2] = bb.x; acc[i][3] = bb.y;
            }
        }
        #pragma unroll 4
        for (int k = 0; k < 128; k++) {
            ulonglong2 wa = *(const ulonglong2*)&ew2s[k * 128 + tx * 8];
            ulonglong2 wb = *(const ulonglong2*)&ew2s[k * 128 + tx * 8 + 4];
            u64t b0 = f2bcast(us[(ey * 4 + 0) * 132 + k]);
            u64t b1 = f2bcast(us[(ey * 4 + 1) * 132 + k]);
            u64t b2 = f2bcast(us[(ey * 4 + 2) * 132 + k]);
            u64t b3 = f2bcast(us[(ey * 4 + 3) * 132 + k]);
            acc[0][0] = f2fma(wa.x, b0, acc[0][0]); acc[0][1] = f2fma(wa.y, b0, acc[0][1]);
            acc[0][2] = f2fma(wb.x, b0, acc[0][2]); acc[0][3] = f2fma(wb.y, b0, acc[0][3]);
            acc[1][0] = f2fma(wa.x, b1, acc[1][0]); acc[1][1] = f2fma(wa.y, b1, acc[1][1]);
            acc[1][2] = f2fma(wb.x, b1, acc[1][2]); acc[1][3] = f2fma(wb.y, b1, acc[1][3]);
            acc[2][0] = f2fma(wa.x, b2, acc[2][0]); acc[2][1] = f2fma(wa.y, b2, acc[2][1]);
            acc[2][2] = f2fma(wb.x, b2, acc[2][2]); acc[2][3] = f2fma(wb.y, b2, acc[2][3]);
            acc[3][0] = f2fma(wa.x, b3, acc[3][0]); acc[3][1] = f2fma(wa.y, b3, acc[3][1]);
            acc[3][2] = f2fma(wb.x, b3, acc[3][2]); acc[3][3] = f2fma(wb.y, b3, acc[3][3]);
        }
        float pd[4] = {0.f, 0.f, 0.f, 0.f};
        {
            const float* wv = &infws[tx * 8];
            #pragma unroll
            for (int i = 0; i < 4; i++) {
                u64t r0 = f2relu(acc[i][0]);
                u64t r1 = f2relu(acc[i][1]);
                u64t r2 = f2relu(acc[i][2]);
                u64t r3 = f2relu(acc[i][3]);
                ulonglong2* op = (ulonglong2*)&ms[(ey * 4 + i) * 132 + tx * 8];
                op[0] = make_ulonglong2(r0, r1);
                op[1] = make_ulonglong2(r2, r3);
                float2 a0 = f2unpack(r0), a1 = f2unpack(r1);
                float2 a2 = f2unpack(r2), a3 = f2unpack(r3);
                pd[i] = a0.x * wv[0] + a0.y * wv[1] + a1.x * wv[2] + a1.y * wv[3]
                      + a2.x * wv[4] + a2.y * wv[5] + a3.x * wv[6] + a3.y * wv[7];
            }
        }
        #pragma unroll
        for (int o = 8; o >= 1; o >>= 1) {
            #pragma unroll
            for (int i = 0; i < 4; i++)
                pd[i] += __shfl_xor_sync(0xFFFFFFFFu, pd[i], o, 16);
        }
        if (tx == 0) {
            #pragma unroll
            for (int i = 0; i < 4; i++)
                eijs[ey * 4 + i] = 1.f / (1.f + expf(-(pd[i] + infb)));
        }
        __syncthreads();

        // ---- coalesced scatter: mi[dst] += mij * eij ----
        for (int idx = tid; idx < TILE_E * H; idx += 256) {
            int e = idx >> 7, c = idx & 127;
            atomicAdd(&g_mi[(size_t)dsts[e] * H + c], ms[e * 132 + c] * eijs[e]);
        }

        // ---- GEMM3: v = relu(mij @ xw1 + xb1); xg = v . xw2 + xb2 ----
        {
            const ulonglong2* bp = (const ulonglong2*)&xb1s[tx * 8];
            ulonglong2 ba = bp[0], bb = bp[1];
            #pragma unroll
            for (int i = 0; i < 4; i++) {
                acc[i][0] = ba.x; acc[i][1] = ba.y; acc[i][2] = bb.x; acc[i][3] = bb.y;
            }
        }
        #pragma unroll 4
        for (int k = 0; k < 128; k++) {
            ulonglong2 wa = *(const ulonglong2*)&xw1s[k * 128 + tx * 8];
            ulonglong2 wb = *(const ulonglong2*)&xw1s[k * 128 + tx * 8 + 4];
            u64t b0 = f2bcast(ms[(ey * 4 + 0) * 132 + k]);
            u64t b1 = f2bcast(ms[(ey * 4 + 1) * 132 + k]);
            u64t b2 = f2bcast(ms[(ey * 4 + 2) * 132 + k]);
            u64t b3 = f2bcast(ms[(ey * 4 + 3) * 132 + k]);
            acc[0][0] = f2fma(wa.x, b0, acc[0][0]); acc[0][1] = f2fma(wa.y, b0, acc[0][1]);
            acc[0][2] = f2fma(wb.x, b0, acc[0][2]); acc[0][3] = f2fma(wb.y, b0, acc[0][3]);
            acc[1][0] = f2fma(wa.x, b1, acc[1][0]); acc[1][1] = f2fma(wa.y, b1, acc[1][1]);
            acc[1][2] = f2fma(wb.x, b1, acc[1][2]); acc[1][3] = f2fma(wb.y, b1, acc[1][3]);
            acc[2][0] = f2fma(wa.x, b2, acc[2][0]); acc[2][1] = f2fma(wa.y, b2, acc[2][1]);
            acc[2][2] = f2fma(wb.x, b2, acc[2][2]); acc[2][3] = f2fma(wb.y, b2, acc[2][3]);
            acc[3][0] = f2fma(wa.x, b3, acc[3][0]); acc[3][1] = f2fma(wa.y, b3, acc[3][1]);
            acc[3][2] = f2fma(wb.x, b3, acc[3][2]); acc[3][3] = f2fma(wb.y, b3, acc[3][3]);
        }
        float pd2[4] = {0.f, 0.f, 0.f, 0.f};
        {
            const float* wv = &xw2s[tx * 8];
            #pragma unroll
            for (int i = 0; i < 4; i++) {
                float2 a0 = f2unpack(acc[i][0]), a1 = f2unpack(acc[i][1]);
                float2 a2 = f2unpack(acc[i][2]), a3 = f2unpack(acc[i][3]);
                pd2[i] = fmaxf(a0.x, 0.f) * wv[0] + fmaxf(a0.y, 0.f) * wv[1]
                       + fmaxf(a1.x, 0.f) * wv[2] + fmaxf(a1.y, 0.f) * wv[3]
                       + fmaxf(a2.x, 0.f) * wv[4] + fmaxf(a2.y, 0.f) * wv[5]
                       + fmaxf(a3.x, 0.f) * wv[6] + fmaxf(a3.y, 0.f) * wv[7];
            }
        }
        #pragma unroll
        for (int o = 8; o >= 1; o >>= 1) {
            #pragma unroll
            for (int i = 0; i < 4; i++)
                pd2[i] += __shfl_xor_sync(0xFFFFFFFFu, pd2[i], o, 16);
        }
        if (tx < 12) {
            int i = tx / 3;
            int c = tx - 3 * i;
            int e = ey * 4 + i;
            float xg = pd2[i] + xb2v;
            atomicAdd(&g_xacc[(size_t)dsts[e] * 3 + c], rels[e * 3 + c] * xg);
        }
    }
}

// =====================================================================
// Kernel 3: node MLP + coordinate write
// =====================================================================
__global__ __launch_bounds__(256, 1) void k_post(
    const float* __restrict__ h,
    const float* __restrict__ x,
    const float* __restrict__ nw1,
    const float* __restrict__ nb1,
    const float* __restrict__ nw2,
    const float* __restrict__ nb2,
    float* __restrict__ out)
{
    extern __shared__ float sm[];
    float* As   = sm;                 // 32*260 = 8320
    float* ws   = As + 32 * 260;      // 64*128 = 8192
    float* ts   = ws + 64 * 128;      // 32*132 = 4224
    float* nw2s = ts + 32 * 132;      // 16384

    const int tid = threadIdx.x;
    const int n0  = blockIdx.x * 32;
    const int tx  = tid & 15;
    const int ny  = tid >> 4;

    {
        int i = blockIdx.x * 256 + tid;
        if (i < N_NODES * 3)
            out[(size_t)N_NODES * H + i] = x[i] + g_xacc[i] * (1.f / (float)N_EDGES);
    }

    for (int i = tid; i < 128 * 128 / 4; i += 256)
        ((float4*)nw2s)[i] = ((const float4*)nw2)[i];
    for (int i = tid; i < 32 * 128 / 4; i += 256) {
        int fi = i * 4;
        int n = fi >> 7, c = fi & 127;
        *(float4*)&As[n * 260 + c]       = *(const float4*)&g_mi[(size_t)(n0 + n) * H + c];
        *(float4*)&As[n * 260 + 128 + c] = *(const float4*)&h[(size_t)(n0 + n) * H + c];
    }

    u64t acc[2][4];
    {
        const ulonglong2* bp = (const ulonglong2*)(nb1 + tx * 8);
        ulonglong2 ba = bp[0], bb = bp[1];
        #pragma unroll
        for (int i = 0; i < 2; i++) {
            acc[i][0] = ba.x; acc[i][1] = ba.y; acc[i][2] = bb.x; acc[i][3] = bb.y;
        }
    }

    for (int kt = 0; kt < 256; kt += 64) {
        __syncthreads();
        for (int i = tid; i < 64 * 128 / 4; i += 256)
            ((float4*)ws)[i] = ((const float4*)(nw1 + (size_t)kt * H))[i];
        __syncthreads();
        #pragma unroll 4
        for (int kk = 0; kk < 64; kk++) {
            u64t b0 = f2bcast(As[(2 * ny + 0) * 260 + kt + kk]);
            u64t b1 = f2bcast(As[(2 * ny + 1) * 260 + kt + kk]);
            ulonglong2 wa = *(const ulonglong2*)&ws[kk * 128 + tx * 8];
            ulonglong2 wb = *(const ulonglong2*)&ws[kk * 128 + tx * 8 + 4];
            acc[0][0] = f2fma(wa.x, b0, acc[0][0]);
            acc[0][1] = f2fma(wa.y, b0, acc[0][1]);
            acc[0][2] = f2fma(wb.x, b0, acc[0][2]);
            acc[0][3] = f2fma(wb.y, b0, acc[0][3]);
            acc[1][0] = f2fma(wa.x, b1, acc[1][0]);
            acc[1][1] = f2fma(wa.y, b1, acc[1][1]);
            acc[1][2] = f2fma(wb.x, b1, acc[1][2]);
            acc[1][3] = f2fma(wb.y, b1, acc[1][3]);
        }
    }
    #pragma unroll
    for (int i = 0; i < 2; i++) {
        ulonglong2* op = (ulonglong2*)&ts[(2 * ny + i) * 132 + tx * 8];
        op[0] = make_ulonglong2(f2relu(acc[i][0]), f2relu(acc[i][1]));
        op[1] = make_ulonglong2(f2relu(acc[i][2]), f2relu(acc[i][3]));
    }
    __syncthreads();

    u64t acc2[2][4];
    {
        const ulonglong2* bp = (const ulonglong2*)(nb2 + tx * 8);
        ulonglong2 ba = bp[0], bb = bp[1];
        #pragma unroll
        for (int i = 0; i < 2; i++) {
            acc2[i][0] = ba.x; acc2[i][1] = ba.y; acc2[i][2] = bb.x; acc2[i][3] = bb.y;
        }
    }
    #pragma unroll 4
    for (int k = 0; k < 128; k++) {
        u64t b0 = f2bcast(ts[(2 * ny + 0) * 132 + k]);
        u64t b1 = f2bcast(ts[(2 * ny + 1) * 132 + k]);
        ulonglong2 wa = *(const ulonglong2*)&nw2s[k * 128 + tx * 8];
        ulonglong2 wb = *(const ulonglong2*)&nw2s[k * 128 + tx * 8 + 4];
        acc2[0][0] = f2fma(wa.x, b0, acc2[0][0]);
        acc2[0][1] = f2fma(wa.y, b0, acc2[0][1]);
        acc2[0][2] = f2fma(wb.x, b0, acc2[0][2]);
        acc2[0][3] = f2fma(wb.y, b0, acc2[0][3]);
        acc2[1][0] = f2fma(wa.x, b1, acc2[1][0]);
        acc2[1][1] = f2fma(wa.y, b1, acc2[1][1]);
        acc2[1][2] = f2fma(wb.x, b1, acc2[1][2]);
        acc2[1][3] = f2fma(wb.y, b1, acc2[1][3]);
    }
    #pragma unroll
    for (int i = 0; i < 2; i++) {
        ulonglong2* op = (ulonglong2*)&out[(size_t)(n0 + 2 * ny + i) * H + tx * 8];
        op[0] = make_ulonglong2(acc2[i][0], acc2[i][1]);
        op[1] = make_ulonglong2(acc2[i][2], acc2[i][3]);
    }
}

// =====================================================================
// launch
// =====================================================================
extern "C" void kernel_launch(void* const* d_in, const int* in_sizes, int n_in,
                              void* d_out, int out_size)
{
    const float* h    = (const float*)d_in[0];
    const float* x    = (const float*)d_in[1];
    const float* ea   = (const float*)d_in[2];
    const float* ew1  = (const float*)d_in[3];
    const float* eb1  = (const float*)d_in[4];
    const float* ew2  = (const float*)d_in[5];
    const float* eb2  = (const float*)d_in[6];
    const float* infw = (const float*)d_in[7];
    const float* infb = (const float*)d_in[8];
    const float* nw1  = (const float*)d_in[9];
    const float* nb1  = (const float*)d_in[10];
    const float* nw2  = (const float*)d_in[11];
    const float* nb2  = (const float*)d_in[12];
    const float* xw1  = (const float*)d_in[13];
    const float* xb1  = (const float*)d_in[14];
    const float* xw2  = (const float*)d_in[15];
    const float* xb2  = (const float*)d_in[16];
    const int*   ei   = (const int*)d_in[17];
    float* out = (float*)d_out;

    const int EDGE_SMEM = 56704 * 4;   // 226816 bytes
    const int POST_SMEM = 37120 * 4;   // 148480 bytes
    cudaFuncSetAttribute(k_edge, cudaFuncAttributeMaxDynamicSharedMemorySize, EDGE_SMEM);
    cudaFuncSetAttribute(k_post, cudaFuncAttributeMaxDynamicSharedMemorySize, POST_SMEM);

    k_pre<<<625, 256>>>(h, ew1, eb1);
    k_edge<<<148, 256, EDGE_SMEM>>>(x, ea, ew1, ew2, eb2, infw, infb,
                                    xw1, xb1, xw2, xb2, ei);
    k_post<<<625, 256, POST_SMEM>>>(h, x, nw1, nb1, nw2, nb2, out);
}

// round 3
// speedup vs baseline: 1.0281x; 1.0281x over previous
#include <cuda_runtime.h>
#include <math.h>

#define N_NODES 20000
#define N_EDGES 320000
#define H 128
#define NRBF 20
#define NATTR 28
#define F48 48            // NATTR + NRBF
#define TILE_E 64
#define NTILES (N_EDGES / TILE_E)   // 5000 exactly

typedef unsigned long long u64t;

// ---------------- packed f32x2 helpers (SASS FFMA2 path) ----------------
__device__ __forceinline__ u64t f2pack(float a, float b) {
    u64t r; asm("mov.b64 %0,{%1,%2};" : "=l"(r) : "f"(a), "f"(b)); return r;
}
__device__ __forceinline__ u64t f2bcast(float a) { return f2pack(a, a); }
__device__ __forceinline__ u64t f2fma(u64t a, u64t b, u64t c) {
    u64t d; asm("fma.rn.f32x2 %0,%1,%2,%3;" : "=l"(d) : "l"(a), "l"(b), "l"(c)); return d;
}
__device__ __forceinline__ u64t f2add(u64t a, u64t b) {
    u64t d; asm("add.rn.f32x2 %0,%1,%2;" : "=l"(d) : "l"(a), "l"(b)); return d;
}
__device__ __forceinline__ float2 f2unpack(u64t v) {
    float2 r; asm("mov.b64 {%0,%1},%2;" : "=f"(r.x), "=f"(r.y) : "l"(v)); return r;
}
__device__ __forceinline__ u64t f2relu(u64t v) {
    float2 t = f2unpack(v);
    return f2pack(fmaxf(t.x, 0.f), fmaxf(t.y, 0.f));
}

// ---------------- device scratch (no dynamic alloc allowed) ----------------
__device__ float g_P[N_NODES * H];     // h @ ew1[48:176] + eb1   (dst part)
__device__ float g_Q[N_NODES * H];     // h @ ew1[176:304]        (src part)
__device__ float g_mi[N_NODES * H];    // segment_sum(mij*eij)
__device__ float g_xacc[N_NODES * 3];  // segment_sum(rel_x*xg)

// =====================================================================
// Kernel 1: P/Q node pre-GEMMs + zero the accumulators
// =====================================================================
__global__ __launch_bounds__(256) void k_pre(
    const float* __restrict__ h,
    const float* __restrict__ ew1,
    const float* __restrict__ eb1)
{
    for (int i = blockIdx.x * 256 + threadIdx.x; i < N_NODES * H; i += gridDim.x * 256)
        g_mi[i] = 0.f;
    for (int i = blockIdx.x * 256 + threadIdx.x; i < N_NODES * 3; i += gridDim.x * 256)
        g_xacc[i] = 0.f;

    __shared__ float hs[32 * 128];
    __shared__ float ws[32 * 128];

    const int tid = threadIdx.x;
    const int n0  = blockIdx.x * 32;
    const int tx  = tid & 15;
    const int ny  = tid >> 4;

    for (int i = tid; i < 32 * 128 / 4; i += 256)
        ((float4*)hs)[i] = ((const float4*)(h + (size_t)n0 * H))[i];

    for (int part = 0; part < 2; part++) {
        u64t acc[2][4];
        if (part == 0) {
            const u64t* bp = (const u64t*)(eb1 + tx * 8);
            u64t b0 = bp[0], b1 = bp[1], b2 = bp[2], b3 = bp[3];
            acc[0][0] = b0; acc[0][1] = b1; acc[0][2] = b2; acc[0][3] = b3;
            acc[1][0] = b0; acc[1][1] = b1; acc[1][2] = b2; acc[1][3] = b3;
        } else {
            #pragma unroll
            for (int i = 0; i < 2; i++)
                #pragma unroll
                for (int j = 0; j < 4; j++) acc[i][j] = 0ull;
        }

        const int roff = (part == 0) ? 48 : 176;
        for (int kt = 0; kt < 128; kt += 32) {
            __syncthreads();
            for (int i = tid; i < 32 * 128 / 4; i += 256)
                ((float4*)ws)[i] = ((const float4*)(ew1 + (size_t)(roff + kt) * H))[i];
            __syncthreads();
            #pragma unroll 4
            for (int kk = 0; kk < 32; kk++) {
                u64t b0 = f2bcast(hs[(2 * ny + 0) * 128 + kt + kk]);
                u64t b1 = f2bcast(hs[(2 * ny + 1) * 128 + kt + kk]);
                ulonglong2 wa = *(const ulonglong2*)&ws[kk * 128 + tx * 8];
                ulonglong2 wb = *(const ulonglong2*)&ws[kk * 128 + tx * 8 + 4];
                acc[0][0] = f2fma(wa.x, b0, acc[0][0]);
                acc[0][1] = f2fma(wa.y, b0, acc[0][1]);
                acc[0][2] = f2fma(wb.x, b0, acc[0][2]);
                acc[0][3] = f2fma(wb.y, b0, acc[0][3]);
                acc[1][0] = f2fma(wa.x, b1, acc[1][0]);
                acc[1][1] = f2fma(wa.y, b1, acc[1][1]);
                acc[1][2] = f2fma(wb.x, b1, acc[1][2]);
                acc[1][3] = f2fma(wb.y, b1, acc[1][3]);
            }
        }
        float* dst = (part == 0) ? g_P : g_Q;
        #pragma unroll
        for (int i = 0; i < 2; i++) {
            ulonglong2* op = (ulonglong2*)&dst[(size_t)(n0 + 2 * ny + i) * H + tx * 8];
            op[0] = make_ulonglong2(acc[i][0], acc[i][1]);
            op[1] = make_ulonglong2(acc[i][2], acc[i][3]);
        }
        __syncthreads();
    }
}

// =====================================================================
// Kernel 2: fused edge kernel (persistent), FFMA2 inner loops
// =====================================================================
__global__ __launch_bounds__(256, 1) void k_edge(
    const float* __restrict__ x,
    const float* __restrict__ edge_attr,
    const float* __restrict__ ew1,
    const float* __restrict__ ew2,
    const float* __restrict__ eb2,
    const float* __restrict__ inf_w,
    const float* __restrict__ inf_b,
    const float* __restrict__ xw1,
    const float* __restrict__ xb1,
    const float* __restrict__ xw2,
    const float* __restrict__ xb2,
    const int* __restrict__ ei)
{
    extern __shared__ float sm[];
    float* ew1s  = sm;                    // 48*128  = 6144
    float* ew2s  = ew1s + 48 * 128;       // 128*128 = 16384
    float* xw1s  = ew2s + 128 * 128;      // 16384
    float* us    = xw1s + 128 * 128;      // 64*132  = 8448
    float* ms    = us + 64 * 132;         // 8448  (f48 aliased inside)
    float* f48s  = ms;                    // 64*49 = 3136 (dead before ms written)
    float* eb2s  = ms + 64 * 132;         // 128
    float* xb1s  = eb2s + 128;            // 128
    float* infws = xb1s + 128;            // 128
    float* xw2s  = infws + 128;           // 128
    float* eijs  = xw2s + 128;            // 64
    float* rels  = eijs + 64;             // 192
    int*   dsts  = (int*)(rels + 192);    // 64
    int*   srcs  = dsts + 64;             // 64

    const int tid = threadIdx.x;

    for (int i = tid; i < 48 * 128 / 4; i += 256)  ((float4*)ew1s)[i] = ((const float4*)ew1)[i];
    for (int i = tid; i < 128 * 128 / 4; i += 256) ((float4*)ew2s)[i] = ((const float4*)ew2)[i];
    for (int i = tid; i < 128 * 128 / 4; i += 256) ((float4*)xw1s)[i] = ((const float4*)xw1)[i];
    if (tid < 128) {
        eb2s[tid]  = eb2[tid];
        xb1s[tid]  = xb1[tid];
        infws[tid] = inf_w[tid];
        xw2s[tid]  = xw2[tid];
    }
    const float infb = inf_b[0];
    const float xb2v = xb2[0];

    const int tx = tid & 15;   // cols tx*8 .. tx*8+7
    const int ey = tid >> 4;   // edges ey*4 .. ey*4+3

    const float OFFSTEP = 100.f / 19.f;
    const float COEFF   = -0.5f / (OFFSTEP * OFFSTEP);

    for (int t = blockIdx.x; t < NTILES; t += gridDim.x) {
        const int e0 = t * TILE_E;
        __syncthreads();

        // ---- stage edge_attr + rbf + indices + rel_x ----
        for (int i = tid; i < TILE_E * NATTR; i += 256) {
            int e = i / NATTR, k = i - e * NATTR;
            f48s[e * 49 + k] = edge_attr[(size_t)(e0 + e) * NATTR + k];
        }
        if (tid < TILE_E) {
            int e = e0 + tid;
            int d = ei[e], s = ei[N_EDGES + e];
            dsts[tid] = d; srcs[tid] = s;
            float rx = x[d * 3 + 0] - x[s * 3 + 0];
            float ry = x[d * 3 + 1] - x[s * 3 + 1];
            float rz = x[d * 3 + 2] - x[s * 3 + 2];
            rels[tid * 3 + 0] = rx; rels[tid * 3 + 1] = ry; rels[tid * 3 + 2] = rz;
            float l2 = sqrtf(rx * rx + ry * ry + rz * rz);
            #pragma unroll
            for (int k = 0; k < NRBF; k++) {
                float dd = l2 - (float)k * OFFSTEP;
                f48s[tid * 49 + NATTR + k] = expf(COEFF * dd * dd);
            }
        }
        __syncthreads();

        // ---- GEMM1: u = relu(P[dst] + Q[src] + f48 @ ew1[0:48]) ----
        u64t acc[4][4];
        int ed[4];
        #pragma unroll
        for (int i = 0; i < 4; i++) ed[i] = dsts[ey * 4 + i];
        #pragma unroll
        for (int i = 0; i < 4; i++) {
            int s = srcs[ey * 4 + i];
            const ulonglong2* Pp = (const ulonglong2*)(g_P + (size_t)ed[i] * H + tx * 8);
            const ulonglong2* Qp = (const ulonglong2*)(g_Q + (size_t)s * H + tx * 8);
            ulonglong2 p0 = Pp[0], p1 = Pp[1];
            ulonglong2 q0 = Qp[0], q1 = Qp[1];
            acc[i][0] = f2add(p0.x, q0.x);
            acc[i][1] = f2add(p0.y, q0.y);
            acc[i][2] = f2add(p1.x, q1.x);
            acc[i][3] = f2add(p1.y, q1.y);
        }
        #pragma unroll 4
        for (int k = 0; k < F48; k++) {
            ulonglong2 wa = *(const ulonglong2*)&ew1s[k * 128 + tx * 8];
            ulonglong2 wb = *(const ulonglong2*)&ew1s[k * 128 + tx * 8 + 4];
            u64t b0 = f2bcast(f48s[(ey * 4 + 0) * 49 + k]);
            u64t b1 = f2bcast(f48s[(ey * 4 + 1) * 49 + k]);
            u64t b2 = f2bcast(f48s[(ey * 4 + 2) * 49 + k]);
            u64t b3 = f2bcast(f48s[(ey * 4 + 3) * 49 + k]);
            acc[0][0] = f2fma(wa.x, b0, acc[0][0]); acc[0][1] = f2fma(wa.y, b0, acc[0][1]);
            acc[0][2] = f2fma(wb.x, b0, acc[0][2]); acc[0][3] = f2fma(wb.y, b0, acc[0][3]);
            acc[1][0] = f2fma(wa.x, b1, acc[1][0]); acc[1][1] = f2fma(wa.y, b1, acc[1][1]);
            acc[1][2] = f2fma(wb.x, b1, acc[1][2]); acc[1][3] = f2fma(wb.y, b1, acc[1][3]);
            acc[2][0] = f2fma(wa.x, b2, acc[2][0]); acc[2][1] = f2fma(wa.y, b2, acc[2][1]);
            acc[2][2] = f2fma(wb.x, b2, acc[2][2]); acc[2][3] = f2fma(wb.y, b2, acc[2][3]);
            acc[3][0] = f2fma(wa.x, b3, acc[3][0]); acc[3][1] = f2fma(wa.y, b3, acc[3][1]);
            acc[3][2] = f2fma(wb.x, b3, acc[3][2]); acc[3][3] = f2fma(wb.y, b3, acc[3][3]);
        }
        #pragma unroll
        for (int i = 0; i < 4; i++) {
            ulonglong2* op = (ulonglong2*)&us[(ey * 4 + i) * 132 + tx * 8];
            op[0] = make_ulonglong2(f2relu(acc[i][0]), f2relu(acc[i][1]));
            op[1] = make_ulonglong2(f2relu(acc[i][2]), f2relu(acc[i][3]));
        }
        __syncthreads();

        // ---- GEMM2: mij = relu(u @ ew2 + eb2); eij ----
        {
            const ulonglong2* bp = (const ulonglong2*)&eb2s[tx * 8];
            ulonglong2 ba = bp[0], bb = bp[1];
            #pragma unroll
            for (int i = 0; i < 4; i++) {
                acc[i][0] = ba.x; acc[i][1] = ba.y; acc[i][2] = bb.x; acc[i][3] = bb.y;
            }
        }
        #pragma unroll 4
        for (int k = 0; k < 128; k++) {
            ulonglong2 wa = *(const ulonglong2*)&ew2s[k * 128 + tx * 8];
            ulonglong2 wb = *(const ulonglong2*)&ew2s[k * 128 + tx * 8 + 4];
            u64t b0 = f2bcast(us[(ey * 4 + 0) * 132 + k]);
            u64t b1 = f2bcast(us[(ey * 4 + 1) * 132 + k]);
            u64t b2 = f2bcast(us[(ey * 4 + 2) * 132 + k]);
            u64t b3 = f2bcast(us[(ey * 4 + 3) * 132 + k]);
            acc[0][0] = f2fma(wa.x, b0, acc[0][0]); acc[0][1] = f2fma(wa.y, b0, acc[0][1]);
            acc[0][2] = f2fma(wb.x, b0, acc[0][2]); acc[0][3] = f2fma(wb.y, b0, acc[0][3]);
            acc[1][0] = f2fma(wa.x, b1, acc[1][0]); acc[1][1] = f2fma(wa.y, b1, acc[1][1]);
            acc[1][2] = f2fma(wb.x, b1, acc[1][2]); acc[1][3] = f2fma(wb.y, b1, acc[1][3]);
            acc[2][0] = f2fma(wa.x, b2, acc[2][0]); acc[2][1] = f2fma(wa.y, b2, acc[2][1]);
            acc[2][2] = f2fma(wb.x, b2, acc[2][2]); acc[2][3] = f2fma(wb.y, b2, acc[2][3]);
            acc[3][0] = f2fma(wa.x, b3, acc[3][0]); acc[3][1] = f2fma(wa.y, b3, acc[3][1]);
            acc[3][2] = f2fma(wb.x, b3, acc[3][2]); acc[3][3] = f2fma(wb.y, b3, acc[3][3]);
        }
        float pd[4] = {0.f, 0.f, 0.f, 0.f};
        {
            const float* wv = &infws[tx * 8];
            #pragma unroll
            for (int i = 0; i < 4; i++) {
                u64t r0 = f2relu(acc[i][0]);
                u64t r1 = f2relu(acc[i][1]);
                u64t r2 = f2relu(acc[i][2]);
                u64t r3 = f2relu(acc[i][3]);
                ulonglong2* op = (ulonglong2*)&ms[(ey * 4 + i) * 132 + tx * 8];
                op[0] = make_ulonglong2(r0, r1);
                op[1] = make_ulonglong2(r2, r3);
                float2 a0 = f2unpack(r0), a1 = f2unpack(r1);
                float2 a2 = f2unpack(r2), a3 = f2unpack(r3);
                pd[i] = a0.x * wv[0] + a0.y * wv[1] + a1.x * wv[2] + a1.y * wv[3]
                      + a2.x * wv[4] + a2.y * wv[5] + a3.x * wv[6] + a3.y * wv[7];
            }
        }
        #pragma unroll
        for (int o = 8; o >= 1; o >>= 1) {
            #pragma unroll
            for (int i = 0; i < 4; i++)
                pd[i] += __shfl_xor_sync(0xFFFFFFFFu, pd[i], o, 16);
        }
        if (tx == 0) {
            #pragma unroll
            for (int i = 0; i < 4; i++)
                eijs[ey * 4 + i] = 1.f / (1.f + expf(-(pd[i] + infb)));
        }
        __syncthreads();

        // ---- coalesced scatter: mi[dst] += mij * eij ----
        for (int idx = tid; idx < TILE_E * H; idx += 256) {
            int e = idx >> 7, c = idx & 127;
            atomicAdd(&g_mi[(size_t)dsts[e] * H + c], ms[e * 132 + c] * eijs[e]);
        }

        // ---- GEMM3: v = relu(mij @ xw1 + xb1); xg = v . xw2 + xb2 ----
        {
            const ulonglong2* bp = (const ulonglong2*)&xb1s[tx * 8];
            ulonglong2 ba = bp[0], bb = bp[1];
            #pragma unroll
            for (int i = 0; i < 4; i++) {
                acc[i][0] = ba.x; acc[i][1] = ba.y; acc[i][2] = bb.x; acc[i][3] = bb.y;
            }
        }
        #pragma unroll 4
        for (int k = 0; k < 128; k++) {
            ulonglong2 wa = *(const ulonglong2*)&xw1s[k * 128 + tx * 8];
            ulonglong2 wb = *(const ulonglong2*)&xw1s[k * 128 + tx * 8 + 4];
            u64t b0 = f2bcast(ms[(ey * 4 + 0) * 132 + k]);
            u64t b1 = f2bcast(ms[(ey * 4 + 1) * 132 + k]);
            u64t b2 = f2bcast(ms[(ey * 4 + 2) * 132 + k]);
            u64t b3 = f2bcast(ms[(ey * 4 + 3) * 132 + k]);
            acc[0][0] = f2fma(wa.x, b0, acc[0][0]); acc[0][1] = f2fma(wa.y, b0, acc[0][1]);
            acc[0][2] = f2fma(wb.x, b0, acc[0][2]); acc[0][3] = f2fma(wb.y, b0, acc[0][3]);
            acc[1][0] = f2fma(wa.x, b1, acc[1][0]); acc[1][1] = f2fma(wa.y, b1, acc[1][1]);
            acc[1][2] = f2fma(wb.x, b1, acc[1][2]); acc[1][3] = f2fma(wb.y, b1, acc[1][3]);
            acc[2][0] = f2fma(wa.x, b2, acc[2][0]); acc[2][1] = f2fma(wa.y, b2, acc[2][1]);
            acc[2][2] = f2fma(wb.x, b2, acc[2][2]); acc[2][3] = f2fma(wb.y, b2, acc[2][3]);
            acc[3][0] = f2fma(wa.x, b3, acc[3][0]); acc[3][1] = f2fma(wa.y, b3, acc[3][1]);
            acc[3][2] = f2fma(wb.x, b3, acc[3][2]); acc[3][3] = f2fma(wb.y, b3, acc[3][3]);
        }
        float pd2[4] = {0.f, 0.f, 0.f, 0.f};
        {
            const float* wv = &xw2s[tx * 8];
            #pragma unroll
            for (int i = 0; i < 4; i++) {
                float2 a0 = f2unpack(acc[i][0]), a1 = f2unpack(acc[i][1]);
                float2 a2 = f2unpack(acc[i][2]), a3 = f2unpack(acc[i][3]);
                pd2[i] = fmaxf(a0.x, 0.f) * wv[0] + fmaxf(a0.y, 0.f) * wv[1]
                       + fmaxf(a1.x, 0.f) * wv[2] + fmaxf(a1.y, 0.f) * wv[3]
                       + fmaxf(a2.x, 0.f) * wv[4] + fmaxf(a2.y, 0.f) * wv[5]
                       + fmaxf(a3.x, 0.f) * wv[6] + fmaxf(a3.y, 0.f) * wv[7];
            }
        }
        #pragma unroll
        for (int o = 8; o >= 1; o >>= 1) {
            #pragma unroll
            for (int i = 0; i < 4; i++)
                pd2[i] += __shfl_xor_sync(0xFFFFFFFFu, pd2[i], o, 16);
        }
        if (tx < 12) {
            int i = tx / 3;
            int c = tx - 3 * i;
            int e = ey * 4 + i;
            float xg = pd2[i] + xb2v;
            atomicAdd(&g_xacc[(size_t)dsts[e] * 3 + c], rels[e * 3 + c] * xg);
        }
    }
}

// =====================================================================
// Kernel 3: node MLP + coordinate write
// =====================================================================
__global__ __launch_bounds__(256, 1) void k_post(
    const float* __restrict__ h,
    const float* __restrict__ x,
    const float* __restrict__ nw1,
    const float* __restrict__ nb1,
    const float* __restrict__ nw2,
    const float* __restrict__ nb2,
    float* __restrict__ out)
{
    extern __shared__ float sm[];
    float* As   = sm;                 // 32*260 = 8320
    float* ws   = As + 32 * 260;      // 64*128 = 8192
    float* ts   = ws + 64 * 128;      // 32*132 = 4224
    float* nw2s = ts + 32 * 132;      // 16384

    const int tid = threadIdx.x;
    const int n0  = blockIdx.x * 32;
    const int tx  = tid & 15;
    const int ny  = tid >> 4;

    {
        int i = blockIdx.x * 256 + tid;
        if (i < N_NODES * 3)
            out[(size_t)N_NODES * H + i] = x[i] + g_xacc[i] * (1.f / (float)N_EDGES);
    }

    for (int i = tid; i < 128 * 128 / 4; i += 256)
        ((float4*)nw2s)[i] = ((const float4*)nw2)[i];
    for (int i = tid; i < 32 * 128 / 4; i += 256) {
        int fi = i * 4;
        int n = fi >> 7, c = fi & 127;
        *(float4*)&As[n * 260 + c]       = *(const float4*)&g_mi[(size_t)(n0 + n) * H + c];
        *(float4*)&As[n * 260 + 128 + c] = *(const float4*)&h[(size_t)(n0 + n) * H + c];
    }

    u64t acc[2][4];
    {
        const ulonglong2* bp = (const ulonglong2*)(nb1 + tx * 8);
        ulonglong2 ba = bp[0], bb = bp[1];
        #pragma unroll
        for (int i = 0; i < 2; i++) {
            acc[i][0] = ba.x; acc[i][1] = ba.y; acc[i][2] = bb.x; acc[i][3] = bb.y;
        }
    }

    for (int kt = 0; kt < 256; kt += 64) {
        __syncthreads();
        for (int i = tid; i < 64 * 128 / 4; i += 256)
            ((float4*)ws)[i] = ((const float4*)(nw1 + (size_t)kt * H))[i];
        __syncthreads();
        #pragma unroll 4
        for (int kk = 0; kk < 64; kk++) {
            u64t b0 = f2bcast(As[(2 * ny + 0) * 260 + kt + kk]);
            u64t b1 = f2bcast(As[(2 * ny + 1) * 260 + kt + kk]);
            ulonglong2 wa = *(const ulonglong2*)&ws[kk * 128 + tx * 8];
            ulonglong2 wb = *(const ulonglong2*)&ws[kk * 128 + tx * 8 + 4];
            acc[0][0] = f2fma(wa.x, b0, acc[0][0]);
            acc[0][1] = f2fma(wa.y, b0, acc[0][1]);
            acc[0][2] = f2fma(wb.x, b0, acc[0][2]);
            acc[0][3] = f2fma(wb.y, b0, acc[0][3]);
            acc[1][0] = f2fma(wa.x, b1, acc[1][0]);
            acc[1][1] = f2fma(wa.y, b1, acc[1][1]);
            acc[1][2] = f2fma(wb.x, b1, acc[1][2]);
            acc[1][3] = f2fma(wb.y, b1, acc[1][3]);
        }
    }
    #pragma unroll
    for (int i = 0; i < 2; i++) {
        ulonglong2* op = (ulonglong2*)&ts[(2 * ny + i) * 132 + tx * 8];
        op[0] = make_ulonglong2(f2relu(acc[i][0]), f2relu(acc[i][1]));
        op[1] = make_ulonglong2(f2relu(acc[i][2]), f2relu(acc[i][3]));
    }
    __syncthreads();

    u64t acc2[2][4];
    {
        const ulonglong2* bp = (const ulonglong2*)(nb2 + tx * 8);
        ulonglong2 ba = bp[0], bb = bp[1];
        #pragma unroll
        for (int i = 0; i < 2; i++) {
            acc2[i][0] = ba.x; acc2[i][1] = ba.y; acc2[i][2] = bb.x; acc2[i][3] = bb.y;
        }
    }
    #pragma unroll 4
    for (int k = 0; k < 128; k++) {
        u64t b0 = f2bcast(ts[(2 * ny + 0) * 132 + k]);
        u64t b1 = f2bcast(ts[(2 * ny + 1) * 132 + k]);
        ulonglong2 wa = *(const ulonglong2*)&nw2s[k * 128 + tx * 8];
        ulonglong2 wb = *(const ulonglong2*)&nw2s[k * 128 + tx * 8 + 4];
        acc2[0][0] = f2fma(wa.x, b0, acc2[0][0]);
        acc2[0][1] = f2fma(wa.y, b0, acc2[0][1]);
        acc2[0][2] = f2fma(wb.x, b0, acc2[0][2]);
        acc2[0][3] = f2fma(wb.y, b0, acc2[0][3]);
        acc2[1][0] = f2fma(wa.x, b1, acc2[1][0]);
        acc2[1][1] = f2fma(wa.y, b1, acc2[1][1]);
        acc2[1][2] = f2fma(wb.x, b1, acc2[1][2]);
        acc2[1][3] = f2fma(wb.y, b1, acc2[1][3]);
    }
    #pragma unroll
    for (int i = 0; i < 2; i++) {
        ulonglong2* op = (ulonglong2*)&out[(size_t)(n0 + 2 * ny + i) * H + tx * 8];
        op[0] = make_ulonglong2(acc2[i][0], acc2[i][1]);
        op[1] = make_ulonglong2(acc2[i][2], acc2[i][3]);
    }
}

// =====================================================================
// launch
// =====================================================================
extern "C" void kernel_launch(void* const* d_in, const int* in_sizes, int n_in,
                              void* d_out, int out_size)
{
    const float* h    = (const float*)d_in[0];
    const float* x    = (const float*)d_in[1];
    const float* ea   = (const float*)d_in[2];
    const float* ew1  = (const float*)d_in[3];
    const float* eb1  = (const float*)d_in[4];
    const float* ew2  = (const float*)d_in[5];
    const float* eb2  = (const float*)d_in[6];
    const float* infw = (const float*)d_in[7];
    const float* infb = (const float*)d_in[8];
    const float* nw1  = (const float*)d_in[9];
    const float* nb1  = (const float*)d_in[10];
    const float* nw2  = (const float*)d_in[11];
    const float* nb2  = (const float*)d_in[12];
    const float* xw1  = (const float*)d_in[13];
    const float* xb1  = (const float*)d_in[14];
    const float* xw2  = (const float*)d_in[15];
    const float* xb2  = (const float*)d_in[16];
    const int*   ei   = (const int*)d_in[17];
    float* out = (float*)d_out;

    const int EDGE_SMEM = 56704 * 4;   // 226816 bytes
    const int POST_SMEM = 37120 * 4;   // 148480 bytes
    cudaFuncSetAttribute(k_edge, cudaFuncAttributeMaxDynamicSharedMemorySize, EDGE_SMEM);
    cudaFuncSetAttribute(k_post, cudaFuncAttributeMaxDynamicSharedMemorySize, POST_SMEM);

    k_pre<<<625, 256>>>(h, ew1, eb1);
    k_edge<<<148, 256, EDGE_SMEM>>>(x, ea, ew1, ew2, eb2, infw, infb,
                                    xw1, xb1, xw2, xb2, ei);
    k_post<<<625, 256, POST_SMEM>>>(h, x, nw1, nb1, nw2, nb2, out);
}

// round 6
// speedup vs baseline: 2.1985x; 2.1385x over previous
#include <cuda_runtime.h>
#include <math.h>
#include <stdint.h>

#define N_NODES 20000
#define N_EDGES 320000
#define H 128
#define NRBF 20
#define NATTR 28
#define TILE_E 128
#define NTILES (N_EDGES / TILE_E)   // 2500

__device__ float g_P[N_NODES * H];
__device__ float g_Q[N_NODES * H];
__device__ float g_mi[N_NODES * H];
__device__ float g_xacc[N_NODES * 3];

__device__ __forceinline__ unsigned tf32cvt(float f) {
    unsigned u; asm("cvt.rna.tf32.f32 %0, %1;" : "=r"(u) : "f"(f)); return u;
}
#define MMA8(c, a0,a1,a2,a3, b0,b1) \
    asm volatile("mma.sync.aligned.m16n8k8.row.col.f32.tf32.tf32.f32 " \
        "{%0,%1,%2,%3},{%4,%5,%6,%7},{%8,%9},{%0,%1,%2,%3};" \
        : "+f"((c)[0]),"+f"((c)[1]),"+f"((c)[2]),"+f"((c)[3]) \
        : "r"(a0),"r"(a1),"r"(a2),"r"(a3),"r"(b0),"r"(b1))

__device__ __forceinline__ void red2(float* p, float a, float b) {
    asm volatile("red.global.add.v2.f32 [%0], {%1,%2};" :: "l"(p), "f"(a), "f"(b) : "memory");
}
__device__ __forceinline__ void red1(float* p, float a) {
    asm volatile("red.global.add.f32 [%0], %1;" :: "l"(p), "f"(a) : "memory");
}

// =====================================================================
// Kernel 1: P/Q node pre-GEMMs (fp32) + zero accumulators
// =====================================================================
__global__ __launch_bounds__(256) void k_pre(
    const float* __restrict__ h, const float* __restrict__ ew1, const float* __restrict__ eb1)
{
    for (int i = blockIdx.x * 256 + threadIdx.x; i < N_NODES * H; i += gridDim.x * 256)
        g_mi[i] = 0.f;
    for (int i = blockIdx.x * 256 + threadIdx.x; i < N_NODES * 3; i += gridDim.x * 256)
        g_xacc[i] = 0.f;

    __shared__ float hs[32 * 128];
    __shared__ float ws[32 * 128];
    const int tid = threadIdx.x;
    const int n0 = blockIdx.x * 32;
    const int tx = tid & 15, ny = tid >> 4;

    for (int i = tid; i < 32 * 128 / 4; i += 256)
        ((float4*)hs)[i] = ((const float4*)(h + (size_t)n0 * H))[i];

    for (int part = 0; part < 2; part++) {
        float acc[2][8];
        #pragma unroll
        for (int i = 0; i < 2; i++)
            #pragma unroll
            for (int j = 0; j < 8; j++)
                acc[i][j] = (part == 0) ? eb1[tx * 8 + j] : 0.f;
        const int roff = (part == 0) ? 48 : 176;
        for (int kt = 0; kt < 128; kt += 32) {
            __syncthreads();
            for (int i = tid; i < 32 * 128 / 4; i += 256)
                ((float4*)ws)[i] = ((const float4*)(ew1 + (size_t)(roff + kt) * H))[i];
            __syncthreads();
            #pragma unroll 4
            for (int kk = 0; kk < 32; kk++) {
                float u0 = hs[(2 * ny + 0) * 128 + kt + kk];
                float u1 = hs[(2 * ny + 1) * 128 + kt + kk];
                float w[8];
                *(float4*)&w[0] = *(float4*)&ws[kk * 128 + tx * 8];
                *(float4*)&w[4] = *(float4*)&ws[kk * 128 + tx * 8 + 4];
                #pragma unroll
                for (int j = 0; j < 8; j++) { acc[0][j] += u0 * w[j]; acc[1][j] += u1 * w[j]; }
            }
        }
        float* dst = (part == 0) ? g_P : g_Q;
        #pragma unroll
        for (int i = 0; i < 2; i++) {
            *(float4*)&dst[(size_t)(n0+2*ny+i)*H + tx*8]   = make_float4(acc[i][0],acc[i][1],acc[i][2],acc[i][3]);
            *(float4*)&dst[(size_t)(n0+2*ny+i)*H + tx*8+4] = make_float4(acc[i][4],acc[i][5],acc[i][6],acc[i][7]);
        }
        __syncthreads();
    }
}

// =====================================================================
// Kernel 2: edge kernel — warp-level tf32 MMA (m16n8k8), persistent
// =====================================================================
// smem offsets in 4-byte units
#define SM_B1  0        // ew1[0:48] frag-permuted: 6ks*16nt*32*2   = 6144
#define SM_B2  6144     // ew2 frag-permuted:      16*16*32*2       = 16384
#define SM_B3  22528    // xw1 frag-permuted                        = 16384
#define SM_AU  38912    // activation tile [128][132] (f48/u/mij)   = 16896
#define SM_EB2 55808
#define SM_XB1 55936
#define SM_INF 56064
#define SM_XW2 56192
#define SM_REL 56320    // 384
#define SM_PD  56704    // 128*4 partials (pd, then pd2)
#define SM_EIJ 57216    // 128
#define SM_DST 57344    // 128 (int)
#define SM_SRC 57472    // 128 (int)
#define SM_TOT 57600    // 230400 bytes

__global__ __launch_bounds__(256, 1) void k_edge(
    const float* __restrict__ x, const float* __restrict__ edge_attr,
    const float* __restrict__ ew1, const float* __restrict__ ew2,
    const float* __restrict__ eb2, const float* __restrict__ inf_w,
    const float* __restrict__ inf_b, const float* __restrict__ xw1,
    const float* __restrict__ xb1, const float* __restrict__ xw2,
    const float* __restrict__ xb2, const int* __restrict__ ei)
{
    extern __shared__ float smf[];
    unsigned* smu = (unsigned*)smf;
    int* smi = (int*)smf;

    const int tid = threadIdx.x, wid = tid >> 5, lane = tid & 31;
    const int g = lane >> 2, tig = lane & 3;
    const int mh = wid & 1, nq = wid >> 1;   // m-half (64 rows), n-quarter (32 cols)

    // ---- stage weights in fragment-permuted order (once) ----
    for (int idx = tid; idx < 3072; idx += 256) {          // B1: 6 ksteps
        int ks = idx >> 9, rem = idx & 511, nt = rem >> 5, ln = rem & 31;
        int k = ks * 8 + (ln & 3), n = nt * 8 + (ln >> 2);
        smu[SM_B1 + idx*2]   = tf32cvt(ew1[k * H + n]);
        smu[SM_B1 + idx*2+1] = tf32cvt(ew1[(k + 4) * H + n]);
    }
    for (int idx = tid; idx < 8192; idx += 256) {          // B2, B3: 16 ksteps
        int ks = idx >> 9, nt = (idx >> 5) & 15, ln = idx & 31;
        int k = ks * 8 + (ln & 3), n = nt * 8 + (ln >> 2);
        smu[SM_B2 + idx*2]   = tf32cvt(ew2[k * H + n]);
        smu[SM_B2 + idx*2+1] = tf32cvt(ew2[(k + 4) * H + n]);
        smu[SM_B3 + idx*2]   = tf32cvt(xw1[k * H + n]);
        smu[SM_B3 + idx*2+1] = tf32cvt(xw1[(k + 4) * H + n]);
    }
    if (tid < 128) {
        smf[SM_EB2 + tid] = eb2[tid];
        smf[SM_XB1 + tid] = xb1[tid];
        smf[SM_INF + tid] = inf_w[tid];
        smf[SM_XW2 + tid] = xw2[tid];
    }
    const float infb = inf_b[0], xb2v = xb2[0];
    const float OFFSTEP = 100.f / 19.f;
    const float COEFF = -0.5f / (OFFSTEP * OFFSTEP);

    const unsigned aub = SM_AU + (unsigned)(g * 132 + tig);  // A-frag base for this thread
    const int rwarp = mh * 64;                               // first row of warp's half

    for (int t = blockIdx.x; t < NTILES; t += gridDim.x) {
        const int e0 = t * TILE_E;
        __syncthreads();   // all warps done with previous tile

        // ---- stage f48 (tf32), indices, rel ----
        for (int i = tid; i < TILE_E * NATTR; i += 256) {
            int r = i / NATTR, k = i - r * NATTR;
            smu[SM_AU + r * 132 + k] = tf32cvt(edge_attr[(size_t)(e0 + r) * NATTR + k]);
        }
        if (tid < TILE_E) {
            int e = e0 + tid;
            int d = ei[e], s = ei[N_EDGES + e];
            smi[SM_DST + tid] = d;
            smi[SM_SRC + tid] = s;
            float rx = x[d*3+0]-x[s*3+0], ry = x[d*3+1]-x[s*3+1], rz = x[d*3+2]-x[s*3+2];
            smf[SM_REL + tid*3+0] = rx; smf[SM_REL + tid*3+1] = ry; smf[SM_REL + tid*3+2] = rz;
            float l2 = sqrtf(rx*rx + ry*ry + rz*rz);
            #pragma unroll
            for (int k = 0; k < NRBF; k++) {
                float dd = l2 - (float)k * OFFSTEP;
                smu[SM_AU + tid * 132 + NATTR + k] = tf32cvt(expf(COEFF * dd * dd));
            }
        }
        __syncthreads();

        float acc[4][4][4];

        // ================= GEMM1: D = f48 @ ew1[0:48]  (K=48) =================
        #pragma unroll
        for (int mi = 0; mi < 4; mi++)
            #pragma unroll
            for (int ni = 0; ni < 4; ni++)
                #pragma unroll
                for (int c = 0; c < 4; c++) acc[mi][ni][c] = 0.f;

        #pragma unroll 2
        for (int ks = 0; ks < 6; ks++) {
            unsigned bf[4][2];
            #pragma unroll
            for (int ni = 0; ni < 4; ni++) {
                uint2 b = *(const uint2*)&smu[SM_B1 + ((ks*16 + nq*4 + ni)*32 + lane)*2];
                bf[ni][0] = b.x; bf[ni][1] = b.y;
            }
            #pragma unroll
            for (int mi = 0; mi < 4; mi++) {
                unsigned r0 = aub + (unsigned)((rwarp + mi*16) * 132 + ks*8);
                unsigned a0 = smu[r0], a1 = smu[r0 + 8*132];
                unsigned a2 = smu[r0 + 4], a3 = smu[r0 + 8*132 + 4];
                #pragma unroll
                for (int ni = 0; ni < 4; ni++)
                    MMA8(acc[mi][ni], a0, a1, a2, a3, bf[ni][0], bf[ni][1]);
            }
        }
        __syncthreads();   // f48 reads done everywhere before u overwrites

        // epi1: u = relu(D + P[dst] + Q[src]) -> SM_AU (tf32)
        #pragma unroll
        for (int mi = 0; mi < 4; mi++) {
            int r0 = rwarp + mi*16 + g, r1 = r0 + 8;
            int d0 = smi[SM_DST + r0], d1 = smi[SM_DST + r1];
            int s0 = smi[SM_SRC + r0], s1 = smi[SM_SRC + r1];
            #pragma unroll
            for (int ni = 0; ni < 4; ni++) {
                int col0 = (nq*4 + ni)*8 + 2*tig;
                float2 p0 = *(const float2*)&g_P[(size_t)d0*H + col0];
                float2 q0 = *(const float2*)&g_Q[(size_t)s0*H + col0];
                float2 p1 = *(const float2*)&g_P[(size_t)d1*H + col0];
                float2 q1 = *(const float2*)&g_Q[(size_t)s1*H + col0];
                float v0 = fmaxf(acc[mi][ni][0] + p0.x + q0.x, 0.f);
                float v1 = fmaxf(acc[mi][ni][1] + p0.y + q0.y, 0.f);
                float v2 = fmaxf(acc[mi][ni][2] + p1.x + q1.x, 0.f);
                float v3 = fmaxf(acc[mi][ni][3] + p1.y + q1.y, 0.f);
                *(uint2*)&smu[SM_AU + r0*132 + col0] = make_uint2(tf32cvt(v0), tf32cvt(v1));
                *(uint2*)&smu[SM_AU + r1*132 + col0] = make_uint2(tf32cvt(v2), tf32cvt(v3));
            }
        }
        __syncthreads();

        // ================= GEMM2: D = u @ ew2 + eb2  (K=128) =================
        #pragma unroll
        for (int ni = 0; ni < 4; ni++) {
            int col0 = (nq*4 + ni)*8 + 2*tig;
            float b0 = smf[SM_EB2 + col0], b1 = smf[SM_EB2 + col0 + 1];
            #pragma unroll
            for (int mi = 0; mi < 4; mi++) {
                acc[mi][ni][0] = b0; acc[mi][ni][1] = b1;
                acc[mi][ni][2] = b0; acc[mi][ni][3] = b1;
            }
        }
        #pragma unroll 2
        for (int ks = 0; ks < 16; ks++) {
            unsigned bf[4][2];
            #pragma unroll
            for (int ni = 0; ni < 4; ni++) {
                uint2 b = *(const uint2*)&smu[SM_B2 + ((ks*16 + nq*4 + ni)*32 + lane)*2];
                bf[ni][0] = b.x; bf[ni][1] = b.y;
            }
            #pragma unroll
            for (int mi = 0; mi < 4; mi++) {
                unsigned r0 = aub + (unsigned)((rwarp + mi*16) * 132 + ks*8);
                unsigned a0 = smu[r0], a1 = smu[r0 + 8*132];
                unsigned a2 = smu[r0 + 4], a3 = smu[r0 + 8*132 + 4];
                #pragma unroll
                for (int ni = 0; ni < 4; ni++)
                    MMA8(acc[mi][ni], a0, a1, a2, a3, bf[ni][0], bf[ni][1]);
            }
        }
        __syncthreads();   // u reads done before mij overwrites

        // epi2: mij = relu(D); pd partials; store tf32 mij; keep fp32 in regs
        {
            float pdp[8] = {0,0,0,0,0,0,0,0};
            #pragma unroll
            for (int mi = 0; mi < 4; mi++) {
                int r0 = rwarp + mi*16 + g, r1 = r0 + 8;
                #pragma unroll
                for (int ni = 0; ni < 4; ni++) {
                    int col0 = (nq*4 + ni)*8 + 2*tig;
                    float w0 = smf[SM_INF + col0], w1 = smf[SM_INF + col0 + 1];
                    float v0 = fmaxf(acc[mi][ni][0], 0.f);
                    float v1 = fmaxf(acc[mi][ni][1], 0.f);
                    float v2 = fmaxf(acc[mi][ni][2], 0.f);
                    float v3 = fmaxf(acc[mi][ni][3], 0.f);
                    acc[mi][ni][0] = v0; acc[mi][ni][1] = v1;
                    acc[mi][ni][2] = v2; acc[mi][ni][3] = v3;
                    pdp[mi*2+0] += v0 * w0 + v1 * w1;
                    pdp[mi*2+1] += v2 * w0 + v3 * w1;
                    *(uint2*)&smu[SM_AU + r0*132 + col0] = make_uint2(tf32cvt(v0), tf32cvt(v1));
                    *(uint2*)&smu[SM_AU + r1*132 + col0] = make_uint2(tf32cvt(v2), tf32cvt(v3));
                }
            }
            #pragma unroll
            for (int o = 1; o <= 2; o <<= 1)
                #pragma unroll
                for (int s = 0; s < 8; s++)
                    pdp[s] += __shfl_xor_sync(0xFFFFFFFFu, pdp[s], o);
            if (tig == 0) {
                #pragma unroll
                for (int mi = 0; mi < 4; mi++) {
                    smf[SM_PD + (rwarp + mi*16 + g    ) * 4 + nq] = pdp[mi*2+0];
                    smf[SM_PD + (rwarp + mi*16 + g + 8) * 4 + nq] = pdp[mi*2+1];
                }
            }
        }
        __syncthreads();

        if (tid < 128) {
            float s = smf[SM_PD + tid*4] + smf[SM_PD + tid*4+1]
                    + smf[SM_PD + tid*4+2] + smf[SM_PD + tid*4+3];
            smf[SM_EIJ + tid] = 1.f / (1.f + expf(-(s + infb)));
        }
        __syncthreads();

        // scatter mi[dst] += mij * eij (fire-and-forget, drains during GEMM3)
        #pragma unroll
        for (int mi = 0; mi < 4; mi++) {
            int r0 = rwarp + mi*16 + g, r1 = r0 + 8;
            int d0 = smi[SM_DST + r0], d1 = smi[SM_DST + r1];
            float e0v = smf[SM_EIJ + r0], e1v = smf[SM_EIJ + r1];
            #pragma unroll
            for (int ni = 0; ni < 4; ni++) {
                int col0 = (nq*4 + ni)*8 + 2*tig;
                red2(&g_mi[(size_t)d0*H + col0], acc[mi][ni][0]*e0v, acc[mi][ni][1]*e0v);
                red2(&g_mi[(size_t)d1*H + col0], acc[mi][ni][2]*e1v, acc[mi][ni][3]*e1v);
            }
        }

        // ================= GEMM3: D = mij @ xw1 + xb1  (K=128) =================
        #pragma unroll
        for (int ni = 0; ni < 4; ni++) {
            int col0 = (nq*4 + ni)*8 + 2*tig;
            float b0 = smf[SM_XB1 + col0], b1 = smf[SM_XB1 + col0 + 1];
            #pragma unroll
            for (int mi = 0; mi < 4; mi++) {
                acc[mi][ni][0] = b0; acc[mi][ni][1] = b1;
                acc[mi][ni][2] = b0; acc[mi][ni][3] = b1;
            }
        }
        #pragma unroll 2
        for (int ks = 0; ks < 16; ks++) {
            unsigned bf[4][2];
            #pragma unroll
            for (int ni = 0; ni < 4; ni++) {
                uint2 b = *(const uint2*)&smu[SM_B3 + ((ks*16 + nq*4 + ni)*32 + lane)*2];
                bf[ni][0] = b.x; bf[ni][1] = b.y;
            }
            #pragma unroll
            for (int mi = 0; mi < 4; mi++) {
                unsigned r0 = aub + (unsigned)((rwarp + mi*16) * 132 + ks*8);
                unsigned a0 = smu[r0], a1 = smu[r0 + 8*132];
                unsigned a2 = smu[r0 + 4], a3 = smu[r0 + 8*132 + 4];
                #pragma unroll
                for (int ni = 0; ni < 4; ni++)
                    MMA8(acc[mi][ni], a0, a1, a2, a3, bf[ni][0], bf[ni][1]);
            }
        }

        // epi3: pd2 partials = relu(D) . xw2
        {
            float pdp[8] = {0,0,0,0,0,0,0,0};
            #pragma unroll
            for (int mi = 0; mi < 4; mi++)
                #pragma unroll
                for (int ni = 0; ni < 4; ni++) {
                    int col0 = (nq*4 + ni)*8 + 2*tig;
                    float w0 = smf[SM_XW2 + col0], w1 = smf[SM_XW2 + col0 + 1];
                    pdp[mi*2+0] += fmaxf(acc[mi][ni][0],0.f)*w0 + fmaxf(acc[mi][ni][1],0.f)*w1;
                    pdp[mi*2+1] += fmaxf(acc[mi][ni][2],0.f)*w0 + fmaxf(acc[mi][ni][3],0.f)*w1;
                }
            #pragma unroll
            for (int o = 1; o <= 2; o <<= 1)
                #pragma unroll
                for (int s = 0; s < 8; s++)
                    pdp[s] += __shfl_xor_sync(0xFFFFFFFFu, pdp[s], o);
            if (tig == 0) {
                #pragma unroll
                for (int mi = 0; mi < 4; mi++) {
                    smf[SM_PD + (rwarp + mi*16 + g    ) * 4 + nq] = pdp[mi*2+0];
                    smf[SM_PD + (rwarp + mi*16 + g + 8) * 4 + nq] = pdp[mi*2+1];
                }
            }
        }
        __syncthreads();

        if (tid < 128) {
            float xg = smf[SM_PD + tid*4] + smf[SM_PD + tid*4+1]
                     + smf[SM_PD + tid*4+2] + smf[SM_PD + tid*4+3] + xb2v;
            int dv = smi[SM_DST + tid];
            red1(&g_xacc[(size_t)dv*3 + 0], smf[SM_REL + tid*3+0] * xg);
            red1(&g_xacc[(size_t)dv*3 + 1], smf[SM_REL + tid*3+1] * xg);
            red1(&g_xacc[(size_t)dv*3 + 2], smf[SM_REL + tid*3+2] * xg);
        }
    }
}

// =====================================================================
// Kernel 3: node MLP + coordinate write (fp32)
// =====================================================================
__global__ __launch_bounds__(256, 1) void k_post(
    const float* __restrict__ h, const float* __restrict__ x,
    const float* __restrict__ nw1, const float* __restrict__ nb1,
    const float* __restrict__ nw2, const float* __restrict__ nb2,
    float* __restrict__ out)
{
    extern __shared__ float sm[];
    float* As   = sm;
    float* ws   = As + 32 * 260;
    float* ts   = ws + 64 * 128;
    float* nw2s = ts + 32 * 132;

    const int tid = threadIdx.x;
    const int n0 = blockIdx.x * 32;
    const int tx = tid & 15, ny = tid >> 4;

    {
        int i = blockIdx.x * 256 + tid;
        if (i < N_NODES * 3)
            out[(size_t)N_NODES * H + i] = x[i] + g_xacc[i] * (1.f / (float)N_EDGES);
    }

    for (int i = tid; i < 128 * 128 / 4; i += 256)
        ((float4*)nw2s)[i] = ((const float4*)nw2)[i];
    for (int i = tid; i < 32 * 128 / 4; i += 256) {
        int fi = i * 4;
        int n = fi >> 7, c = fi & 127;
        *(float4*)&As[n * 260 + c]       = *(const float4*)&g_mi[(size_t)(n0 + n) * H + c];
        *(float4*)&As[n * 260 + 128 + c] = *(const float4*)&h[(size_t)(n0 + n) * H + c];
    }

    float acc[2][8];
    #pragma unroll
    for (int i = 0; i < 2; i++)
        #pragma unroll
        for (int j = 0; j < 8; j++)
            acc[i][j] = nb1[tx * 8 + j];

    for (int kt = 0; kt < 256; kt += 64) {
        __syncthreads();
        for (int i = tid; i < 64 * 128 / 4; i += 256)
            ((float4*)ws)[i] = ((const float4*)(nw1 + (size_t)kt * H))[i];
        __syncthreads();
        #pragma unroll 4
        for (int kk = 0; kk < 64; kk++) {
            float u0 = As[(2 * ny + 0) * 260 + kt + kk];
            float u1 = As[(2 * ny + 1) * 260 + kt + kk];
            float w[8];
            *(float4*)&w[0] = *(float4*)&ws[kk * 128 + tx * 8];
            *(float4*)&w[4] = *(float4*)&ws[kk * 128 + tx * 8 + 4];
            #pragma unroll
            for (int j = 0; j < 8; j++) { acc[0][j] += u0 * w[j]; acc[1][j] += u1 * w[j]; }
        }
    }
    #pragma unroll
    for (int i = 0; i < 2; i++) {
        float o[8];
        #pragma unroll
        for (int j = 0; j < 8; j++) o[j] = fmaxf(acc[i][j], 0.f);
        *(float4*)&ts[(2 * ny + i) * 132 + tx * 8]     = *(float4*)&o[0];
        *(float4*)&ts[(2 * ny + i) * 132 + tx * 8 + 4] = *(float4*)&o[4];
    }
    __syncthreads();

    float acc2[2][8];
    #pragma unroll
    for (int i = 0; i < 2; i++)
        #pragma unroll
        for (int j = 0; j < 8; j++)
            acc2[i][j] = nb2[tx * 8 + j];
    #pragma unroll 4
    for (int k = 0; k < 128; k++) {
        float u0 = ts[(2 * ny + 0) * 132 + k];
        float u1 = ts[(2 * ny + 1) * 132 + k];
        float w[8];
        *(float4*)&w[0] = *(float4*)&nw2s[k * 128 + tx * 8];
        *(float4*)&w[4] = *(float4*)&nw2s[k * 128 + tx * 8 + 4];
        #pragma unroll
        for (int j = 0; j < 8; j++) { acc2[0][j] += u0 * w[j]; acc2[1][j] += u1 * w[j]; }
    }
    #pragma unroll
    for (int i = 0; i < 2; i++) {
        *(float4*)&out[(size_t)(n0+2*ny+i)*H + tx*8]   = make_float4(acc2[i][0],acc2[i][1],acc2[i][2],acc2[i][3]);
        *(float4*)&out[(size_t)(n0+2*ny+i)*H + tx*8+4] = make_float4(acc2[i][4],acc2[i][5],acc2[i][6],acc2[i][7]);
    }
}

// =====================================================================
extern "C" void kernel_launch(void* const* d_in, const int* in_sizes, int n_in,
                              void* d_out, int out_size)
{
    const float* h    = (const float*)d_in[0];
    const float* x    = (const float*)d_in[1];
    const float* ea   = (const float*)d_in[2];
    const float* ew1  = (const float*)d_in[3];
    const float* eb1  = (const float*)d_in[4];
    const float* ew2  = (const float*)d_in[5];
    const float* eb2  = (const float*)d_in[6];
    const float* infw = (const float*)d_in[7];
    const float* infb = (const float*)d_in[8];
    const float* nw1  = (const float*)d_in[9];
    const float* nb1  = (const float*)d_in[10];
    const float* nw2  = (const float*)d_in[11];
    const float* nb2  = (const float*)d_in[12];
    const float* xw1  = (const float*)d_in[13];
    const float* xb1  = (const float*)d_in[14];
    const float* xw2  = (const float*)d_in[15];
    const float* xb2  = (const float*)d_in[16];
    const int*   ei   = (const int*)d_in[17];
    float* out = (float*)d_out;

    const int EDGE_SMEM = SM_TOT * 4;     // 230400 bytes
    const int POST_SMEM = 37120 * 4;
    cudaFuncSetAttribute(k_edge, cudaFuncAttributeMaxDynamicSharedMemorySize, EDGE_SMEM);
    cudaFuncSetAttribute(k_post, cudaFuncAttributeMaxDynamicSharedMemorySize, POST_SMEM);

    k_pre<<<625, 256>>>(h, ew1, eb1);
    k_edge<<<148, 256, EDGE_SMEM>>>(x, ea, ew1, ew2, eb2, infw, infb,
                                    xw1, xb1, xw2, xb2, ei);
    k_post<<<625, 256, POST_SMEM>>>(h, x, nw1, nb1, nw2, nb2, out);
}

// round 9
// speedup vs baseline: 2.9920x; 1.3609x over previous
#include <cuda_runtime.h>
#include <cuda_fp16.h>
#include <math.h>
#include <stdint.h>

#define N_NODES 20000
#define N_EDGES 320000
#define H 128
#define NRBF 20
#define NATTR 28
#define TILE_E 128
#define NTILES (N_EDGES / TILE_E)   // 2500

__device__ float g_P[N_NODES * H];
__device__ float g_Q[N_NODES * H];
__device__ float g_mi[N_NODES * H];
__device__ float g_xacc[N_NODES * 3];

__device__ __forceinline__ unsigned h2pack(float a, float b) {
    __half2 v = __floats2half2_rn(a, b);
    return *(unsigned*)&v;
}
#define MMA16(c, a0,a1,a2,a3, b0,b1) \
    asm volatile("mma.sync.aligned.m16n8k16.row.col.f32.f16.f16.f32 " \
        "{%0,%1,%2,%3},{%4,%5,%6,%7},{%8,%9},{%0,%1,%2,%3};" \
        : "+f"((c)[0]),"+f"((c)[1]),"+f"((c)[2]),"+f"((c)[3]) \
        : "r"(a0),"r"(a1),"r"(a2),"r"(a3),"r"(b0),"r"(b1))

__device__ __forceinline__ void red2(float* p, float a, float b) {
    asm volatile("red.global.add.v2.f32 [%0], {%1,%2};" :: "l"(p), "f"(a), "f"(b) : "memory");
}
__device__ __forceinline__ void red1(float* p, float a) {
    asm volatile("red.global.add.f32 [%0], %1;" :: "l"(p), "f"(a) : "memory");
}

// =====================================================================
// Kernel 1: P/Q node pre-GEMMs via fp16 MMA + zero accumulators
//   A = h[128 nodes x 128 k] (fp16), B = ew1[48:304] (256 cols), fp32 acc
// =====================================================================
#define PRE_B 0          // 8 ks * 32 nt * 32 lanes * 2 u32 = 16384
#define PRE_A 16384      // 128 * 68 u32 (half2)             = 8704
#define PRE_BIAS 25088   // 128
#define PRE_TOT 25216    // 100864 bytes
#define PRE_GRID 157

__global__ __launch_bounds__(256, 1) void k_pre(
    const float* __restrict__ h, const float* __restrict__ ew1, const float* __restrict__ eb1)
{
    extern __shared__ float smf[];
    unsigned* smu = (unsigned*)smf;

    // zero global accumulators
    for (int i = blockIdx.x * 256 + threadIdx.x; i < N_NODES * H; i += PRE_GRID * 256)
        g_mi[i] = 0.f;
    for (int i = blockIdx.x * 256 + threadIdx.x; i < N_NODES * 3; i += PRE_GRID * 256)
        g_xacc[i] = 0.f;

    const int tid = threadIdx.x, wid = tid >> 5, lane = tid & 31;
    const int g = lane >> 2, tig = lane & 3;
    const int mh = wid & 1, nq = wid >> 1;
    const int n0 = blockIdx.x * 128;

    // stage B fragments: 256 output cols (0..127 -> P via ew1[48+k], 128..255 -> Q via ew1[176+k])
    for (int idx = tid; idx < 8192; idx += 256) {
        int ks = idx >> 10, nt = (idx >> 5) & 31, ln = idx & 31;
        int n = nt * 8 + (ln >> 2);
        int k0 = ks * 16 + 2 * (ln & 3);
        int rbase = (n < 128) ? 48 : 176;
        int nn = n & 127;
        smu[PRE_B + idx*2]   = h2pack(ew1[(rbase + k0    ) * H + nn], ew1[(rbase + k0 + 1) * H + nn]);
        smu[PRE_B + idx*2+1] = h2pack(ew1[(rbase + k0 + 8) * H + nn], ew1[(rbase + k0 + 9) * H + nn]);
    }
    if (tid < 128) smf[PRE_BIAS + tid] = eb1[tid];

    // stage A = h tile (fp16, stride 68 half2)
    for (int idx = tid; idx < 128 * 64; idx += 256) {
        int r = idx >> 6, c = idx & 63;
        int gr = n0 + r;
        float2 v = (gr < N_NODES) ? *(const float2*)&h[(size_t)gr * H + 2 * c] : make_float2(0.f, 0.f);
        smu[PRE_A + r * 68 + c] = h2pack(v.x, v.y);
    }
    __syncthreads();

    float acc[4][8][4];
    #pragma unroll
    for (int ni = 0; ni < 8; ni++) {
        int coln0 = (nq * 8 + ni) * 8 + 2 * tig;
        float b0 = (coln0 < 128) ? smf[PRE_BIAS + coln0] : 0.f;
        float b1 = (coln0 < 128) ? smf[PRE_BIAS + coln0 + 1] : 0.f;
        #pragma unroll
        for (int mi = 0; mi < 4; mi++) {
            acc[mi][ni][0] = b0; acc[mi][ni][1] = b1;
            acc[mi][ni][2] = b0; acc[mi][ni][3] = b1;
        }
    }
    const unsigned aub = PRE_A + (unsigned)(g * 68 + tig);
    const int rwarp = mh * 64;
    #pragma unroll
    for (int ks = 0; ks < 8; ks++) {
        unsigned bf[8][2];
        #pragma unroll
        for (int ni = 0; ni < 8; ni++) {
            uint2 b = *(const uint2*)&smu[PRE_B + ((ks*32 + nq*8 + ni)*32 + lane)*2];
            bf[ni][0] = b.x; bf[ni][1] = b.y;
        }
        #pragma unroll
        for (int mi = 0; mi < 4; mi++) {
            unsigned r0 = aub + (unsigned)((rwarp + mi*16) * 68 + ks*8);
            unsigned a0 = smu[r0], a1 = smu[r0 + 544];
            unsigned a2 = smu[r0 + 4], a3 = smu[r0 + 548];
            #pragma unroll
            for (int ni = 0; ni < 8; ni++)
                MMA16(acc[mi][ni], a0, a1, a2, a3, bf[ni][0], bf[ni][1]);
        }
    }
    // store P/Q (fp32)
    #pragma unroll
    for (int mi = 0; mi < 4; mi++) {
        int r0 = rwarp + mi*16 + g, r1 = r0 + 8;
        int gr0 = n0 + r0, gr1 = n0 + r1;
        #pragma unroll
        for (int ni = 0; ni < 8; ni++) {
            int coln0 = (nq * 8 + ni) * 8 + 2 * tig;
            float* dst = (coln0 < 128) ? g_P : g_Q;
            int cc = coln0 & 127;
            if (gr0 < N_NODES)
                *(float2*)&dst[(size_t)gr0 * H + cc] = make_float2(acc[mi][ni][0], acc[mi][ni][1]);
            if (gr1 < N_NODES)
                *(float2*)&dst[(size_t)gr1 * H + cc] = make_float2(acc[mi][ni][2], acc[mi][ni][3]);
        }
    }
}

// =====================================================================
// Kernel 2: edge kernel — fp16 MMA m16n8k16, persistent
// =====================================================================
// smem offsets in 4-byte units
#define SM_B1  0        // 3 ks * 16 nt * 32 * 2 = 3072
#define SM_B2  3072     // 8 ks * 16 nt * 32 * 2 = 8192
#define SM_B3  11264    // 8192
#define SM_AU  19456    // 128 rows * 68 half2   = 8704
#define SM_EB2 28160
#define SM_XB1 28288
#define SM_INF 28416
#define SM_XW2 28544
#define SM_REL 28672    // 384
#define SM_PD  29056    // 512
#define SM_EIJ 29568    // 128
#define SM_DST 29696    // 128 (int)
#define SM_SRC 29824    // 128 (int)
#define SM_TOT 29952    // 119808 bytes

__global__ __launch_bounds__(256, 1) void k_edge(
    const float* __restrict__ x, const float* __restrict__ edge_attr,
    const float* __restrict__ ew1, const float* __restrict__ ew2,
    const float* __restrict__ eb2, const float* __restrict__ inf_w,
    const float* __restrict__ inf_b, const float* __restrict__ xw1,
    const float* __restrict__ xb1, const float* __restrict__ xw2,
    const float* __restrict__ xb2, const int* __restrict__ ei)
{
    extern __shared__ float smf[];
    unsigned* smu = (unsigned*)smf;
    int* smi = (int*)smf;

    const int tid = threadIdx.x, wid = tid >> 5, lane = tid & 31;
    const int g = lane >> 2, tig = lane & 3;
    const int mh = wid & 1, nq = wid >> 1;

    // ---- stage weights as fp16 fragments (once) ----
    for (int idx = tid; idx < 1536; idx += 256) {          // B1: ew1[0:48], 3 ksteps
        int ks = idx >> 9, rem = idx & 511, nt = rem >> 5, ln = rem & 31;
        int n = nt * 8 + (ln >> 2);
        int k0 = ks * 16 + 2 * (ln & 3);
        smu[SM_B1 + idx*2]   = h2pack(ew1[k0 * H + n], ew1[(k0 + 1) * H + n]);
        smu[SM_B1 + idx*2+1] = h2pack(ew1[(k0 + 8) * H + n], ew1[(k0 + 9) * H + n]);
    }
    for (int idx = tid; idx < 4096; idx += 256) {          // B2, B3: 8 ksteps
        int ks = idx >> 9, nt = (idx >> 5) & 15, ln = idx & 31;
        int n = nt * 8 + (ln >> 2);
        int k0 = ks * 16 + 2 * (ln & 3);
        smu[SM_B2 + idx*2]   = h2pack(ew2[k0 * H + n], ew2[(k0 + 1) * H + n]);
        smu[SM_B2 + idx*2+1] = h2pack(ew2[(k0 + 8) * H + n], ew2[(k0 + 9) * H + n]);
        smu[SM_B3 + idx*2]   = h2pack(xw1[k0 * H + n], xw1[(k0 + 1) * H + n]);
        smu[SM_B3 + idx*2+1] = h2pack(xw1[(k0 + 8) * H + n], xw1[(k0 + 9) * H + n]);
    }
    if (tid < 128) {
        smf[SM_EB2 + tid] = eb2[tid];
        smf[SM_XB1 + tid] = xb1[tid];
        smf[SM_INF + tid] = inf_w[tid];
        smf[SM_XW2 + tid] = xw2[tid];
    }
    const float infb = inf_b[0], xb2v = xb2[0];
    const float OFFSTEP = 100.f / 19.f;
    const float COEFF = -0.5f / (OFFSTEP * OFFSTEP);

    const unsigned aub = SM_AU + (unsigned)(g * 68 + tig);
    const int rwarp = mh * 64;

    for (int t = blockIdx.x; t < NTILES; t += gridDim.x) {
        const int e0 = t * TILE_E;
        __syncthreads();

        // ---- stage f48 (fp16 half2), indices, rel ----
        for (int i = tid; i < TILE_E * 14; i += 256) {     // attr: 14 half2 per row
            int r = i / 14, c2 = i - r * 14;
            float2 v = *(const float2*)&edge_attr[(size_t)(e0 + r) * NATTR + 2 * c2];
            smu[SM_AU + r * 68 + c2] = h2pack(v.x, v.y);
        }
        if (tid < TILE_E) {
            int e = e0 + tid;
            int d = ei[e], s = ei[N_EDGES + e];
            smi[SM_DST + tid] = d;
            smi[SM_SRC + tid] = s;
            float rx = x[d*3+0]-x[s*3+0], ry = x[d*3+1]-x[s*3+1], rz = x[d*3+2]-x[s*3+2];
            smf[SM_REL + tid*3+0] = rx; smf[SM_REL + tid*3+1] = ry; smf[SM_REL + tid*3+2] = rz;
            float l2 = sqrtf(rx*rx + ry*ry + rz*rz);
            float rb[NRBF];
            #pragma unroll
            for (int k = 0; k < NRBF; k++) {
                float dd = l2 - (float)k * OFFSTEP;
                rb[k] = expf(COEFF * dd * dd);
            }
            #pragma unroll
            for (int j = 0; j < 10; j++)
                smu[SM_AU + tid * 68 + 14 + j] = h2pack(rb[2*j], rb[2*j+1]);
        }
        __syncthreads();

        float acc[4][4][4];

        // ================= GEMM1: D = f48 @ ew1[0:48]  (3 ksteps) =================
        #pragma unroll
        for (int mi = 0; mi < 4; mi++)
            #pragma unroll
            for (int ni = 0; ni < 4; ni++)
                #pragma unroll
                for (int c = 0; c < 4; c++) acc[mi][ni][c] = 0.f;

        #pragma unroll
        for (int ks = 0; ks < 3; ks++) {
            unsigned bf[4][2];
            #pragma unroll
            for (int ni = 0; ni < 4; ni++) {
                uint2 b = *(const uint2*)&smu[SM_B1 + ((ks*16 + nq*4 + ni)*32 + lane)*2];
                bf[ni][0] = b.x; bf[ni][1] = b.y;
            }
            #pragma unroll
            for (int mi = 0; mi < 4; mi++) {
                unsigned r0 = aub + (unsigned)((rwarp + mi*16) * 68 + ks*8);
                unsigned a0 = smu[r0], a1 = smu[r0 + 544];
                unsigned a2 = smu[r0 + 4], a3 = smu[r0 + 548];
                #pragma unroll
                for (int ni = 0; ni < 4; ni++)
                    MMA16(acc[mi][ni], a0, a1, a2, a3, bf[ni][0], bf[ni][1]);
            }
        }
        __syncthreads();   // f48 reads done before u overwrites

        // epi1: u = relu(D + P[dst] + Q[src]) -> SM_AU (fp16)
        #pragma unroll
        for (int mi = 0; mi < 4; mi++) {
            int r0 = rwarp + mi*16 + g, r1 = r0 + 8;
            int d0 = smi[SM_DST + r0], d1 = smi[SM_DST + r1];
            int s0 = smi[SM_SRC + r0], s1 = smi[SM_SRC + r1];
            #pragma unroll
            for (int ni = 0; ni < 4; ni++) {
                int col0 = (nq*4 + ni)*8 + 2*tig;
                float2 p0 = *(const float2*)&g_P[(size_t)d0*H + col0];
                float2 q0 = *(const float2*)&g_Q[(size_t)s0*H + col0];
                float2 p1 = *(const float2*)&g_P[(size_t)d1*H + col0];
                float2 q1 = *(const float2*)&g_Q[(size_t)s1*H + col0];
                float v0 = fmaxf(acc[mi][ni][0] + p0.x + q0.x, 0.f);
                float v1 = fmaxf(acc[mi][ni][1] + p0.y + q0.y, 0.f);
                float v2 = fmaxf(acc[mi][ni][2] + p1.x + q1.x, 0.f);
                float v3 = fmaxf(acc[mi][ni][3] + p1.y + q1.y, 0.f);
                int hc = (nq*4 + ni)*4 + tig;
                smu[SM_AU + r0*68 + hc] = h2pack(v0, v1);
                smu[SM_AU + r1*68 + hc] = h2pack(v2, v3);
            }
        }
        __syncthreads();

        // ================= GEMM2: D = u @ ew2 + eb2  (8 ksteps) =================
        #pragma unroll
        for (int ni = 0; ni < 4; ni++) {
            int col0 = (nq*4 + ni)*8 + 2*tig;
            float b0 = smf[SM_EB2 + col0], b1 = smf[SM_EB2 + col0 + 1];
            #pragma unroll
            for (int mi = 0; mi < 4; mi++) {
                acc[mi][ni][0] = b0; acc[mi][ni][1] = b1;
                acc[mi][ni][2] = b0; acc[mi][ni][3] = b1;
            }
        }
        #pragma unroll
        for (int ks = 0; ks < 8; ks++) {
            unsigned bf[4][2];
            #pragma unroll
            for (int ni = 0; ni < 4; ni++) {
                uint2 b = *(const uint2*)&smu[SM_B2 + ((ks*16 + nq*4 + ni)*32 + lane)*2];
                bf[ni][0] = b.x; bf[ni][1] = b.y;
            }
            #pragma unroll
            for (int mi = 0; mi < 4; mi++) {
                unsigned r0 = aub + (unsigned)((rwarp + mi*16) * 68 + ks*8);
                unsigned a0 = smu[r0], a1 = smu[r0 + 544];
                unsigned a2 = smu[r0 + 4], a3 = smu[r0 + 548];
                #pragma unroll
                for (int ni = 0; ni < 4; ni++)
                    MMA16(acc[mi][ni], a0, a1, a2, a3, bf[ni][0], bf[ni][1]);
            }
        }
        __syncthreads();   // u reads done before mij overwrites

        // epi2: mij = relu(D); pd partials; store fp16 mij; keep fp32 in regs
        {
            float pdp[8] = {0,0,0,0,0,0,0,0};
            #pragma unroll
            for (int mi = 0; mi < 4; mi++) {
                int r0 = rwarp + mi*16 + g, r1 = r0 + 8;
                #pragma unroll
                for (int ni = 0; ni < 4; ni++) {
                    int col0 = (nq*4 + ni)*8 + 2*tig;
                    float w0 = smf[SM_INF + col0], w1 = smf[SM_INF + col0 + 1];
                    float v0 = fmaxf(acc[mi][ni][0], 0.f);
                    float v1 = fmaxf(acc[mi][ni][1], 0.f);
                    float v2 = fmaxf(acc[mi][ni][2], 0.f);
                    float v3 = fmaxf(acc[mi][ni][3], 0.f);
                    acc[mi][ni][0] = v0; acc[mi][ni][1] = v1;
                    acc[mi][ni][2] = v2; acc[mi][ni][3] = v3;
                    pdp[mi*2+0] += v0 * w0 + v1 * w1;
                    pdp[mi*2+1] += v2 * w0 + v3 * w1;
                    int hc = (nq*4 + ni)*4 + tig;
                    smu[SM_AU + r0*68 + hc] = h2pack(v0, v1);
                    smu[SM_AU + r1*68 + hc] = h2pack(v2, v3);
                }
            }
            #pragma unroll
            for (int o = 1; o <= 2; o <<= 1)
                #pragma unroll
                for (int s = 0; s < 8; s++)
                    pdp[s] += __shfl_xor_sync(0xFFFFFFFFu, pdp[s], o);
            if (tig == 0) {
                #pragma unroll
                for (int mi = 0; mi < 4; mi++) {
                    smf[SM_PD + (rwarp + mi*16 + g    ) * 4 + nq] = pdp[mi*2+0];
                    smf[SM_PD + (rwarp + mi*16 + g + 8) * 4 + nq] = pdp[mi*2+1];
                }
            }
        }
        __syncthreads();

        if (tid < 128) {
            float s = smf[SM_PD + tid*4] + smf[SM_PD + tid*4+1]
                    + smf[SM_PD + tid*4+2] + smf[SM_PD + tid*4+3];
            smf[SM_EIJ + tid] = 1.f / (1.f + expf(-(s + infb)));
        }
        __syncthreads();

        // scatter mi[dst] += mij * eij (drains during GEMM3)
        #pragma unroll
        for (int mi = 0; mi < 4; mi++) {
            int r0 = rwarp + mi*16 + g, r1 = r0 + 8;
            int d0 = smi[SM_DST + r0], d1 = smi[SM_DST + r1];
            float e0v = smf[SM_EIJ + r0], e1v = smf[SM_EIJ + r1];
            #pragma unroll
            for (int ni = 0; ni < 4; ni++) {
                int col0 = (nq*4 + ni)*8 + 2*tig;
                red2(&g_mi[(size_t)d0*H + col0], acc[mi][ni][0]*e0v, acc[mi][ni][1]*e0v);
                red2(&g_mi[(size_t)d1*H + col0], acc[mi][ni][2]*e1v, acc[mi][ni][3]*e1v);
            }
        }

        // ================= GEMM3: D = mij @ xw1 + xb1  (8 ksteps) =================
        #pragma unroll
        for (int ni = 0; ni < 4; ni++) {
            int col0 = (nq*4 + ni)*8 + 2*tig;
            float b0 = smf[SM_XB1 + col0], b1 = smf[SM_XB1 + col0 + 1];
            #pragma unroll
            for (int mi = 0; mi < 4; mi++) {
                acc[mi][ni][0] = b0; acc[mi][ni][1] = b1;
                acc[mi][ni][2] = b0; acc[mi][ni][3] = b1;
            }
        }
        #pragma unroll
        for (int ks = 0; ks < 8; ks++) {
            unsigned bf[4][2];
            #pragma unroll
            for (int ni = 0; ni < 4; ni++) {
                uint2 b = *(const uint2*)&smu[SM_B3 + ((ks*16 + nq*4 + ni)*32 + lane)*2];
                bf[ni][0] = b.x; bf[ni][1] = b.y;
            }
            #pragma unroll
            for (int mi = 0; mi < 4; mi++) {
                unsigned r0 = aub + (unsigned)((rwarp + mi*16) * 68 + ks*8);
                unsigned a0 = smu[r0], a1 = smu[r0 + 544];
                unsigned a2 = smu[r0 + 4], a3 = smu[r0 + 548];
                #pragma unroll
                for (int ni = 0; ni < 4; ni++)
                    MMA16(acc[mi][ni], a0, a1, a2, a3, bf[ni][0], bf[ni][1]);
            }
        }

        // epi3: pd2 partials = relu(D) . xw2
        {
            float pdp[8] = {0,0,0,0,0,0,0,0};
            #pragma unroll
            for (int mi = 0; mi < 4; mi++)
                #pragma unroll
                for (int ni = 0; ni < 4; ni++) {
                    int col0 = (nq*4 + ni)*8 + 2*tig;
                    float w0 = smf[SM_XW2 + col0], w1 = smf[SM_XW2 + col0 + 1];
                    pdp[mi*2+0] += fmaxf(acc[mi][ni][0],0.f)*w0 + fmaxf(acc[mi][ni][1],0.f)*w1;
                    pdp[mi*2+1] += fmaxf(acc[mi][ni][2],0.f)*w0 + fmaxf(acc[mi][ni][3],0.f)*w1;
                }
            #pragma unroll
            for (int o = 1; o <= 2; o <<= 1)
                #pragma unroll
                for (int s = 0; s < 8; s++)
                    pdp[s] += __shfl_xor_sync(0xFFFFFFFFu, pdp[s], o);
            if (tig == 0) {
                #pragma unroll
                for (int mi = 0; mi < 4; mi++) {
                    smf[SM_PD + (rwarp + mi*16 + g    ) * 4 + nq] = pdp[mi*2+0];
                    smf[SM_PD + (rwarp + mi*16 + g + 8) * 4 + nq] = pdp[mi*2+1];
                }
            }
        }
        __syncthreads();

        if (tid < 128) {
            float xg = smf[SM_PD + tid*4] + smf[SM_PD + tid*4+1]
                     + smf[SM_PD + tid*4+2] + smf[SM_PD + tid*4+3] + xb2v;
            int dv = smi[SM_DST + tid];
            red1(&g_xacc[(size_t)dv*3 + 0], smf[SM_REL + tid*3+0] * xg);
            red1(&g_xacc[(size_t)dv*3 + 1], smf[SM_REL + tid*3+1] * xg);
            red1(&g_xacc[(size_t)dv*3 + 2], smf[SM_REL + tid*3+2] * xg);
        }
    }
}

// =====================================================================
// Kernel 3: node MLP + coordinate write (fp32, exact)
// =====================================================================
__global__ __launch_bounds__(256, 1) void k_post(
    const float* __restrict__ h, const float* __restrict__ x,
    const float* __restrict__ nw1, const float* __restrict__ nb1,
    const float* __restrict__ nw2, const float* __restrict__ nb2,
    float* __restrict__ out)
{
    extern __shared__ float sm[];
    float* As   = sm;
    float* ws   = As + 32 * 260;
    float* ts   = ws + 64 * 128;
    float* nw2s = ts + 32 * 132;

    const int tid = threadIdx.x;
    const int n0 = blockIdx.x * 32;
    const int tx = tid & 15, ny = tid >> 4;

    {
        int i = blockIdx.x * 256 + tid;
        if (i < N_NODES * 3)
            out[(size_t)N_NODES * H + i] = x[i] + g_xacc[i] * (1.f / (float)N_EDGES);
    }

    for (int i = tid; i < 128 * 128 / 4; i += 256)
        ((float4*)nw2s)[i] = ((const float4*)nw2)[i];
    for (int i = tid; i < 32 * 128 / 4; i += 256) {
        int fi = i * 4;
        int n = fi >> 7, c = fi & 127;
        *(float4*)&As[n * 260 + c]       = *(const float4*)&g_mi[(size_t)(n0 + n) * H + c];
        *(float4*)&As[n * 260 + 128 + c] = *(const float4*)&h[(size_t)(n0 + n) * H + c];
    }

    float acc[2][8];
    #pragma unroll
    for (int i = 0; i < 2; i++)
        #pragma unroll
        for (int j = 0; j < 8; j++)
            acc[i][j] = nb1[tx * 8 + j];

    for (int kt = 0; kt < 256; kt += 64) {
        __syncthreads();
        for (int i = tid; i < 64 * 128 / 4; i += 256)
            ((float4*)ws)[i] = ((const float4*)(nw1 + (size_t)kt * H))[i];
        __syncthreads();
        #pragma unroll 4
        for (int kk = 0; kk < 64; kk++) {
            float u0 = As[(2 * ny + 0) * 260 + kt + kk];
            float u1 = As[(2 * ny + 1) * 260 + kt + kk];
            float w[8];
            *(float4*)&w[0] = *(float4*)&ws[kk * 128 + tx * 8];
            *(float4*)&w[4] = *(float4*)&ws[kk * 128 + tx * 8 + 4];
            #pragma unroll
            for (int j = 0; j < 8; j++) { acc[0][j] += u0 * w[j]; acc[1][j] += u1 * w[j]; }
        }
    }
    #pragma unroll
    for (int i = 0; i < 2; i++) {
        float o[8];
        #pragma unroll
        for (int j = 0; j < 8; j++) o[j] = fmaxf(acc[i][j], 0.f);
        *(float4*)&ts[(2 * ny + i) * 132 + tx * 8]     = *(float4*)&o[0];
        *(float4*)&ts[(2 * ny + i) * 132 + tx * 8 + 4] = *(float4*)&o[4];
    }
    __syncthreads();

    float acc2[2][8];
    #pragma unroll
    for (int i = 0; i < 2; i++)
        #pragma unroll
        for (int j = 0; j < 8; j++)
            acc2[i][j] = nb2[tx * 8 + j];
    #pragma unroll 4
    for (int k = 0; k < 128; k++) {
        float u0 = ts[(2 * ny + 0) * 132 + k];
        float u1 = ts[(2 * ny + 1) * 132 + k];
        float w[8];
        *(float4*)&w[0] = *(float4*)&nw2s[k * 128 + tx * 8];
        *(float4*)&w[4] = *(float4*)&nw2s[k * 128 + tx * 8 + 4];
        #pragma unroll
        for (int j = 0; j < 8; j++) { acc2[0][j] += u0 * w[j]; acc2[1][j] += u1 * w[j]; }
    }
    #pragma unroll
    for (int i = 0; i < 2; i++) {
        *(float4*)&out[(size_t)(n0+2*ny+i)*H + tx*8]   = make_float4(acc2[i][0],acc2[i][1],acc2[i][2],acc2[i][3]);
        *(float4*)&out[(size_t)(n0+2*ny+i)*H + tx*8+4] = make_float4(acc2[i][4],acc2[i][5],acc2[i][6],acc2[i][7]);
    }
}

// =====================================================================
extern "C" void kernel_launch(void* const* d_in, const int* in_sizes, int n_in,
                              void* d_out, int out_size)
{
    const float* h    = (const float*)d_in[0];
    const float* x    = (const float*)d_in[1];
    const float* ea   = (const float*)d_in[2];
    const float* ew1  = (const float*)d_in[3];
    const float* eb1  = (const float*)d_in[4];
    const float* ew2  = (const float*)d_in[5];
    const float* eb2  = (const float*)d_in[6];
    const float* infw = (const float*)d_in[7];
    const float* infb = (const float*)d_in[8];
    const float* nw1  = (const float*)d_in[9];
    const float* nb1  = (const float*)d_in[10];
    const float* nw2  = (const float*)d_in[11];
    const float* nb2  = (const float*)d_in[12];
    const float* xw1  = (const float*)d_in[13];
    const float* xb1  = (const float*)d_in[14];
    const float* xw2  = (const float*)d_in[15];
    const float* xb2  = (const float*)d_in[16];
    const int*   ei   = (const int*)d_in[17];
    float* out = (float*)d_out;

    const int PRE_SMEM  = PRE_TOT * 4;    // 100864 bytes
    const int EDGE_SMEM = SM_TOT * 4;     // 119808 bytes
    const int POST_SMEM = 37120 * 4;
    cudaFuncSetAttribute(k_pre,  cudaFuncAttributeMaxDynamicSharedMemorySize, PRE_SMEM);
    cudaFuncSetAttribute(k_edge, cudaFuncAttributeMaxDynamicSharedMemorySize, EDGE_SMEM);
    cudaFuncSetAttribute(k_post, cudaFuncAttributeMaxDynamicSharedMemorySize, POST_SMEM);

    k_pre<<<PRE_GRID, 256, PRE_SMEM>>>(h, ew1, eb1);
    k_edge<<<148, 256, EDGE_SMEM>>>(x, ea, ew1, ew2, eb2, infw, infb,
                                    xw1, xb1, xw2, xb2, ei);
    k_post<<<625, 256, POST_SMEM>>>(h, x, nw1, nb1, nw2, nb2, out);
}

// round 11
// speedup vs baseline: 3.2091x; 1.0726x over previous
#include <cuda_runtime.h>
#include <cuda_fp16.h>
#include <math.h>
#include <stdint.h>

#define N_NODES 20000
#define N_EDGES 320000
#define H 128
#define NRBF 20
#define NATTR 28
#define TILE_E 128
#define NTILES (N_EDGES / TILE_E)   // 2500

__device__ float g_P[N_NODES * H];
__device__ float g_Q[N_NODES * H];
__device__ float g_mi[N_NODES * H];
__device__ float g_xacc[N_NODES * 3];

__device__ __forceinline__ unsigned h2pack(float a, float b) {
    __half2 v = __floats2half2_rn(a, b);
    return *(unsigned*)&v;
}
#define MMA16(c, a0,a1,a2,a3, b0,b1) \
    asm volatile("mma.sync.aligned.m16n8k16.row.col.f32.f16.f16.f32 " \
        "{%0,%1,%2,%3},{%4,%5,%6,%7},{%8,%9},{%0,%1,%2,%3};" \
        : "+f"((c)[0]),"+f"((c)[1]),"+f"((c)[2]),"+f"((c)[3]) \
        : "r"(a0),"r"(a1),"r"(a2),"r"(a3),"r"(b0),"r"(b1))

__device__ __forceinline__ void red2(float* p, float a, float b) {
    asm volatile("red.global.add.v2.f32 [%0], {%1,%2};" :: "l"(p), "f"(a), "f"(b) : "memory");
}
__device__ __forceinline__ void red1(float* p, float a) {
    asm volatile("red.global.add.f32 [%0], %1;" :: "l"(p), "f"(a) : "memory");
}

// =====================================================================
// Kernel 1: P/Q node pre-GEMMs via fp16 MMA + zero accumulators
// =====================================================================
#define PRE_B 0
#define PRE_A 16384
#define PRE_BIAS 25088
#define PRE_TOT 25216
#define PRE_GRID 157

__global__ __launch_bounds__(256, 1) void k_pre(
    const float* __restrict__ h, const float* __restrict__ ew1, const float* __restrict__ eb1)
{
    extern __shared__ float smf[];
    unsigned* smu = (unsigned*)smf;

    for (int i = blockIdx.x * 256 + threadIdx.x; i < N_NODES * H; i += PRE_GRID * 256)
        g_mi[i] = 0.f;
    for (int i = blockIdx.x * 256 + threadIdx.x; i < N_NODES * 3; i += PRE_GRID * 256)
        g_xacc[i] = 0.f;

    const int tid = threadIdx.x, wid = tid >> 5, lane = tid & 31;
    const int g = lane >> 2, tig = lane & 3;
    const int mh = wid & 1, nq = wid >> 1;
    const int n0 = blockIdx.x * 128;

    for (int idx = tid; idx < 8192; idx += 256) {
        int ks = idx >> 10, nt = (idx >> 5) & 31, ln = idx & 31;
        int n = nt * 8 + (ln >> 2);
        int k0 = ks * 16 + 2 * (ln & 3);
        int rbase = (n < 128) ? 48 : 176;
        int nn = n & 127;
        smu[PRE_B + idx*2]   = h2pack(ew1[(rbase + k0    ) * H + nn], ew1[(rbase + k0 + 1) * H + nn]);
        smu[PRE_B + idx*2+1] = h2pack(ew1[(rbase + k0 + 8) * H + nn], ew1[(rbase + k0 + 9) * H + nn]);
    }
    if (tid < 128) smf[PRE_BIAS + tid] = eb1[tid];

    for (int idx = tid; idx < 128 * 64; idx += 256) {
        int r = idx >> 6, c = idx & 63;
        int gr = n0 + r;
        float2 v = (gr < N_NODES) ? *(const float2*)&h[(size_t)gr * H + 2 * c] : make_float2(0.f, 0.f);
        smu[PRE_A + r * 68 + c] = h2pack(v.x, v.y);
    }
    __syncthreads();

    float acc[4][8][4];
    #pragma unroll
    for (int ni = 0; ni < 8; ni++) {
        int coln0 = (nq * 8 + ni) * 8 + 2 * tig;
        float b0 = (coln0 < 128) ? smf[PRE_BIAS + coln0] : 0.f;
        float b1 = (coln0 < 128) ? smf[PRE_BIAS + coln0 + 1] : 0.f;
        #pragma unroll
        for (int mi = 0; mi < 4; mi++) {
            acc[mi][ni][0] = b0; acc[mi][ni][1] = b1;
            acc[mi][ni][2] = b0; acc[mi][ni][3] = b1;
        }
    }
    const unsigned aub = PRE_A + (unsigned)(g * 68 + tig);
    const int rwarp = mh * 64;
    #pragma unroll
    for (int ks = 0; ks < 8; ks++) {
        unsigned bf[8][2];
        #pragma unroll
        for (int ni = 0; ni < 8; ni++) {
            uint2 b = *(const uint2*)&smu[PRE_B + ((ks*32 + nq*8 + ni)*32 + lane)*2];
            bf[ni][0] = b.x; bf[ni][1] = b.y;
        }
        #pragma unroll
        for (int mi = 0; mi < 4; mi++) {
            unsigned r0 = aub + (unsigned)((rwarp + mi*16) * 68 + ks*8);
            unsigned a0 = smu[r0], a1 = smu[r0 + 544];
            unsigned a2 = smu[r0 + 4], a3 = smu[r0 + 548];
            #pragma unroll
            for (int ni = 0; ni < 8; ni++)
                MMA16(acc[mi][ni], a0, a1, a2, a3, bf[ni][0], bf[ni][1]);
        }
    }
    #pragma unroll
    for (int mi = 0; mi < 4; mi++) {
        int r0 = rwarp + mi*16 + g, r1 = r0 + 8;
        int gr0 = n0 + r0, gr1 = n0 + r1;
        #pragma unroll
        for (int ni = 0; ni < 8; ni++) {
            int coln0 = (nq * 8 + ni) * 8 + 2 * tig;
            float* dst = (coln0 < 128) ? g_P : g_Q;
            int cc = coln0 & 127;
            if (gr0 < N_NODES)
                *(float2*)&dst[(size_t)gr0 * H + cc] = make_float2(acc[mi][ni][0], acc[mi][ni][1]);
            if (gr1 < N_NODES)
                *(float2*)&dst[(size_t)gr1 * H + cc] = make_float2(acc[mi][ni][2], acc[mi][ni][3]);
        }
    }
}

// =====================================================================
// Kernel 2: edge kernel — fp16 MMA, 512 threads = 2 independent groups
// =====================================================================
// shared weights (u32 units)
#define SM_B1  0        // 3072
#define SM_B2  3072     // 8192
#define SM_B3  11264    // 8192
#define SM_EB2 19456
#define SM_XB1 19584
#define SM_INF 19712
#define SM_XW2 19840
#define SM_GRP 19968    // per-group region base
// per-group offsets
#define G_AU  0         // 128 * 68 = 8704
#define G_REL 8704      // 384
#define G_PD  9088      // 512
#define G_EIJ 9600      // 128
#define G_DST 9728      // 128
#define G_SRC 9856      // 128
#define GSZ   9984
#define SM_TOT_E (SM_GRP + 2 * GSZ)   // 39936 u32 = 159744 bytes

#define GBAR() asm volatile("bar.sync %0, 256;" :: "r"(grp + 1) : "memory")

__global__ __launch_bounds__(512, 1) void k_edge(
    const float* __restrict__ x, const float* __restrict__ edge_attr,
    const float* __restrict__ ew1, const float* __restrict__ ew2,
    const float* __restrict__ eb2, const float* __restrict__ inf_w,
    const float* __restrict__ inf_b, const float* __restrict__ xw1,
    const float* __restrict__ xb1, const float* __restrict__ xw2,
    const float* __restrict__ xb2, const int* __restrict__ ei)
{
    extern __shared__ float smf[];
    unsigned* smu = (unsigned*)smf;
    int* smi = (int*)smf;

    const int tid = threadIdx.x, wid = tid >> 5, lane = tid & 31;
    const int grp = wid >> 3, gwid = wid & 7;
    const int ltid = tid & 255;
    const int g = lane >> 2, tig = lane & 3;
    const int mh = gwid & 1, nq = gwid >> 1;
    const int gb = SM_GRP + grp * GSZ;

    // ---- stage shared weights (all 512 threads) ----
    for (int idx = tid; idx < 1536; idx += 512) {          // B1: ew1[0:48], 3 ksteps
        int ks = idx >> 9, rem = idx & 511, nt = rem >> 5, ln = rem & 31;
        int n = nt * 8 + (ln >> 2);
        int k0 = ks * 16 + 2 * (ln & 3);
        smu[SM_B1 + idx*2]   = h2pack(ew1[k0 * H + n], ew1[(k0 + 1) * H + n]);
        smu[SM_B1 + idx*2+1] = h2pack(ew1[(k0 + 8) * H + n], ew1[(k0 + 9) * H + n]);
    }
    for (int idx = tid; idx < 4096; idx += 512) {          // B2, B3: 8 ksteps
        int ks = idx >> 9, nt = (idx >> 5) & 15, ln = idx & 31;
        int n = nt * 8 + (ln >> 2);
        int k0 = ks * 16 + 2 * (ln & 3);
        smu[SM_B2 + idx*2]   = h2pack(ew2[k0 * H + n], ew2[(k0 + 1) * H + n]);
        smu[SM_B2 + idx*2+1] = h2pack(ew2[(k0 + 8) * H + n], ew2[(k0 + 9) * H + n]);
        smu[SM_B3 + idx*2]   = h2pack(xw1[k0 * H + n], xw1[(k0 + 1) * H + n]);
        smu[SM_B3 + idx*2+1] = h2pack(xw1[(k0 + 8) * H + n], xw1[(k0 + 9) * H + n]);
    }
    if (tid < 128) {
        smf[SM_EB2 + tid] = eb2[tid];
        smf[SM_XB1 + tid] = xb1[tid];
        smf[SM_INF + tid] = inf_w[tid];
        smf[SM_XW2 + tid] = xw2[tid];
    }
    const float infb = inf_b[0], xb2v = xb2[0];
    const float OFFSTEP = 100.f / 19.f;
    const float COEFF = -0.5f / (OFFSTEP * OFFSTEP);
    __syncthreads();

    const unsigned aub = (unsigned)(gb + G_AU) + (unsigned)(g * 68 + tig);
    const int rwarp = mh * 64;

    for (int t = blockIdx.x * 2 + grp; t < NTILES; t += 296) {
        const int e0 = t * TILE_E;
        GBAR();   // group done with previous tile

        // ---- stage f48 (fp16), indices, rel (group-local) ----
        for (int i = ltid; i < TILE_E * 14; i += 256) {
            int r = i / 14, c2 = i - r * 14;
            float2 v = *(const float2*)&edge_attr[(size_t)(e0 + r) * NATTR + 2 * c2];
            smu[gb + G_AU + r * 68 + c2] = h2pack(v.x, v.y);
        }
        if (ltid < TILE_E) {
            int e = e0 + ltid;
            int d = ei[e], s = ei[N_EDGES + e];
            smi[gb + G_DST + ltid] = d;
            smi[gb + G_SRC + ltid] = s;
            float rx = x[d*3+0]-x[s*3+0], ry = x[d*3+1]-x[s*3+1], rz = x[d*3+2]-x[s*3+2];
            smf[gb + G_REL + ltid*3+0] = rx;
            smf[gb + G_REL + ltid*3+1] = ry;
            smf[gb + G_REL + ltid*3+2] = rz;
            float l2 = sqrtf(rx*rx + ry*ry + rz*rz);
            float rb[NRBF];
            #pragma unroll
            for (int k = 0; k < NRBF; k++) {
                float dd = l2 - (float)k * OFFSTEP;
                rb[k] = expf(COEFF * dd * dd);
            }
            #pragma unroll
            for (int j = 0; j < 10; j++)
                smu[gb + G_AU + ltid * 68 + 14 + j] = h2pack(rb[2*j], rb[2*j+1]);
        }
        GBAR();

        float acc[4][4][4];

        // ===== GEMM1: D = f48 @ ew1[0:48]  (3 ksteps) =====
        #pragma unroll
        for (int mi = 0; mi < 4; mi++)
            #pragma unroll
            for (int ni = 0; ni < 4; ni++)
                #pragma unroll
                for (int c = 0; c < 4; c++) acc[mi][ni][c] = 0.f;

        #pragma unroll
        for (int ks = 0; ks < 3; ks++) {
            unsigned bf[4][2];
            #pragma unroll
            for (int ni = 0; ni < 4; ni++) {
                uint2 b = *(const uint2*)&smu[SM_B1 + ((ks*16 + nq*4 + ni)*32 + lane)*2];
                bf[ni][0] = b.x; bf[ni][1] = b.y;
            }
            #pragma unroll
            for (int mi = 0; mi < 4; mi++) {
                unsigned r0 = aub + (unsigned)((rwarp + mi*16) * 68 + ks*8);
                unsigned a0 = smu[r0], a1 = smu[r0 + 544];
                unsigned a2 = smu[r0 + 4], a3 = smu[r0 + 548];
                #pragma unroll
                for (int ni = 0; ni < 4; ni++)
                    MMA16(acc[mi][ni], a0, a1, a2, a3, bf[ni][0], bf[ni][1]);
            }
        }
        GBAR();   // f48 reads done before u overwrites

        // epi1: u = relu(D + P[dst] + Q[src]) -> AU (fp16)
        #pragma unroll
        for (int mi = 0; mi < 4; mi++) {
            int r0 = rwarp + mi*16 + g, r1 = r0 + 8;
            int d0 = smi[gb + G_DST + r0], d1 = smi[gb + G_DST + r1];
            int s0 = smi[gb + G_SRC + r0], s1 = smi[gb + G_SRC + r1];
            #pragma unroll
            for (int ni = 0; ni < 4; ni++) {
                int col0 = (nq*4 + ni)*8 + 2*tig;
                float2 p0 = *(const float2*)&g_P[(size_t)d0*H + col0];
                float2 q0 = *(const float2*)&g_Q[(size_t)s0*H + col0];
                float2 p1 = *(const float2*)&g_P[(size_t)d1*H + col0];
                float2 q1 = *(const float2*)&g_Q[(size_t)s1*H + col0];
                float v0 = fmaxf(acc[mi][ni][0] + p0.x + q0.x, 0.f);
                float v1 = fmaxf(acc[mi][ni][1] + p0.y + q0.y, 0.f);
                float v2 = fmaxf(acc[mi][ni][2] + p1.x + q1.x, 0.f);
                float v3 = fmaxf(acc[mi][ni][3] + p1.y + q1.y, 0.f);
                int hc = (nq*4 + ni)*4 + tig;
                smu[gb + G_AU + r0*68 + hc] = h2pack(v0, v1);
                smu[gb + G_AU + r1*68 + hc] = h2pack(v2, v3);
            }
        }
        GBAR();

        // ===== GEMM2: D = u @ ew2 + eb2  (8 ksteps) =====
        #pragma unroll
        for (int ni = 0; ni < 4; ni++) {
            int col0 = (nq*4 + ni)*8 + 2*tig;
            float b0 = smf[SM_EB2 + col0], b1 = smf[SM_EB2 + col0 + 1];
            #pragma unroll
            for (int mi = 0; mi < 4; mi++) {
                acc[mi][ni][0] = b0; acc[mi][ni][1] = b1;
                acc[mi][ni][2] = b0; acc[mi][ni][3] = b1;
            }
        }
        #pragma unroll
        for (int ks = 0; ks < 8; ks++) {
            unsigned bf[4][2];
            #pragma unroll
            for (int ni = 0; ni < 4; ni++) {
                uint2 b = *(const uint2*)&smu[SM_B2 + ((ks*16 + nq*4 + ni)*32 + lane)*2];
                bf[ni][0] = b.x; bf[ni][1] = b.y;
            }
            #pragma unroll
            for (int mi = 0; mi < 4; mi++) {
                unsigned r0 = aub + (unsigned)((rwarp + mi*16) * 68 + ks*8);
                unsigned a0 = smu[r0], a1 = smu[r0 + 544];
                unsigned a2 = smu[r0 + 4], a3 = smu[r0 + 548];
                #pragma unroll
                for (int ni = 0; ni < 4; ni++)
                    MMA16(acc[mi][ni], a0, a1, a2, a3, bf[ni][0], bf[ni][1]);
            }
        }
        GBAR();   // u reads done before mij overwrites

        // epi2: mij = relu(D); pd partials; store fp16 mij
        {
            float pdp[8] = {0,0,0,0,0,0,0,0};
            #pragma unroll
            for (int mi = 0; mi < 4; mi++) {
                int r0 = rwarp + mi*16 + g, r1 = r0 + 8;
                #pragma unroll
                for (int ni = 0; ni < 4; ni++) {
                    int col0 = (nq*4 + ni)*8 + 2*tig;
                    float w0 = smf[SM_INF + col0], w1 = smf[SM_INF + col0 + 1];
                    float v0 = fmaxf(acc[mi][ni][0], 0.f);
                    float v1 = fmaxf(acc[mi][ni][1], 0.f);
                    float v2 = fmaxf(acc[mi][ni][2], 0.f);
                    float v3 = fmaxf(acc[mi][ni][3], 0.f);
                    acc[mi][ni][0] = v0; acc[mi][ni][1] = v1;
                    acc[mi][ni][2] = v2; acc[mi][ni][3] = v3;
                    pdp[mi*2+0] += v0 * w0 + v1 * w1;
                    pdp[mi*2+1] += v2 * w0 + v3 * w1;
                    int hc = (nq*4 + ni)*4 + tig;
                    smu[gb + G_AU + r0*68 + hc] = h2pack(v0, v1);
                    smu[gb + G_AU + r1*68 + hc] = h2pack(v2, v3);
                }
            }
            #pragma unroll
            for (int o = 1; o <= 2; o <<= 1)
                #pragma unroll
                for (int s = 0; s < 8; s++)
                    pdp[s] += __shfl_xor_sync(0xFFFFFFFFu, pdp[s], o);
            if (tig == 0) {
                #pragma unroll
                for (int mi = 0; mi < 4; mi++) {
                    smf[gb + G_PD + (rwarp + mi*16 + g    ) * 4 + nq] = pdp[mi*2+0];
                    smf[gb + G_PD + (rwarp + mi*16 + g + 8) * 4 + nq] = pdp[mi*2+1];
                }
            }
        }
        GBAR();

        if (ltid < 128) {
            float s = smf[gb + G_PD + ltid*4] + smf[gb + G_PD + ltid*4+1]
                    + smf[gb + G_PD + ltid*4+2] + smf[gb + G_PD + ltid*4+3];
            smf[gb + G_EIJ + ltid] = 1.f / (1.f + expf(-(s + infb)));
        }
        GBAR();

        // scatter mi[dst] += mij * eij (drains during GEMM3)
        #pragma unroll
        for (int mi = 0; mi < 4; mi++) {
            int r0 = rwarp + mi*16 + g, r1 = r0 + 8;
            int d0 = smi[gb + G_DST + r0], d1 = smi[gb + G_DST + r1];
            float e0v = smf[gb + G_EIJ + r0], e1v = smf[gb + G_EIJ + r1];
            #pragma unroll
            for (int ni = 0; ni < 4; ni++) {
                int col0 = (nq*4 + ni)*8 + 2*tig;
                red2(&g_mi[(size_t)d0*H + col0], acc[mi][ni][0]*e0v, acc[mi][ni][1]*e0v);
                red2(&g_mi[(size_t)d1*H + col0], acc[mi][ni][2]*e1v, acc[mi][ni][3]*e1v);
            }
        }

        // ===== GEMM3: D = mij @ xw1 + xb1  (8 ksteps) =====
        #pragma unroll
        for (int ni = 0; ni < 4; ni++) {
            int col0 = (nq*4 + ni)*8 + 2*tig;
            float b0 = smf[SM_XB1 + col0], b1 = smf[SM_XB1 + col0 + 1];
            #pragma unroll
            for (int mi = 0; mi < 4; mi++) {
                acc[mi][ni][0] = b0; acc[mi][ni][1] = b1;
                acc[mi][ni][2] = b0; acc[mi][ni][3] = b1;
            }
        }
        #pragma unroll
        for (int ks = 0; ks < 8; ks++) {
            unsigned bf[4][2];
            #pragma unroll
            for (int ni = 0; ni < 4; ni++) {
                uint2 b = *(const uint2*)&smu[SM_B3 + ((ks*16 + nq*4 + ni)*32 + lane)*2];
                bf[ni][0] = b.x; bf[ni][1] = b.y;
            }
            #pragma unroll
            for (int mi = 0; mi < 4; mi++) {
                unsigned r0 = aub + (unsigned)((rwarp + mi*16) * 68 + ks*8);
                unsigned a0 = smu[r0], a1 = smu[r0 + 544];
                unsigned a2 = smu[r0 + 4], a3 = smu[r0 + 548];
                #pragma unroll
                for (int ni = 0; ni < 4; ni++)
                    MMA16(acc[mi][ni], a0, a1, a2, a3, bf[ni][0], bf[ni][1]);
            }
        }

        // epi3: pd2 partials = relu(D) . xw2
        {
            float pdp[8] = {0,0,0,0,0,0,0,0};
            #pragma unroll
            for (int mi = 0; mi < 4; mi++)
                #pragma unroll
                for (int ni = 0; ni < 4; ni++) {
                    int col0 = (nq*4 + ni)*8 + 2*tig;
                    float w0 = smf[SM_XW2 + col0], w1 = smf[SM_XW2 + col0 + 1];
                    pdp[mi*2+0] += fmaxf(acc[mi][ni][0],0.f)*w0 + fmaxf(acc[mi][ni][1],0.f)*w1;
                    pdp[mi*2+1] += fmaxf(acc[mi][ni][2],0.f)*w0 + fmaxf(acc[mi][ni][3],0.f)*w1;
                }
            #pragma unroll
            for (int o = 1; o <= 2; o <<= 1)
                #pragma unroll
                for (int s = 0; s < 8; s++)
                    pdp[s] += __shfl_xor_sync(0xFFFFFFFFu, pdp[s], o);
            if (tig == 0) {
                #pragma unroll
                for (int mi = 0; mi < 4; mi++) {
                    smf[gb + G_PD + (rwarp + mi*16 + g    ) * 4 + nq] = pdp[mi*2+0];
                    smf[gb + G_PD + (rwarp + mi*16 + g + 8) * 4 + nq] = pdp[mi*2+1];
                }
            }
        }
        GBAR();

        if (ltid < 128) {
            float xg = smf[gb + G_PD + ltid*4] + smf[gb + G_PD + ltid*4+1]
                     + smf[gb + G_PD + ltid*4+2] + smf[gb + G_PD + ltid*4+3] + xb2v;
            int dv = smi[gb + G_DST + ltid];
            red1(&g_xacc[(size_t)dv*3 + 0], smf[gb + G_REL + ltid*3+0] * xg);
            red1(&g_xacc[(size_t)dv*3 + 1], smf[gb + G_REL + ltid*3+1] * xg);
            red1(&g_xacc[(size_t)dv*3 + 2], smf[gb + G_REL + ltid*3+2] * xg);
        }
    }
}

// =====================================================================
// Kernel 3: node MLP + coordinate write (fp32, exact)
// =====================================================================
__global__ __launch_bounds__(256, 1) void k_post(
    const float* __restrict__ h, const float* __restrict__ x,
    const float* __restrict__ nw1, const float* __restrict__ nb1,
    const float* __restrict__ nw2, const float* __restrict__ nb2,
    float* __restrict__ out)
{
    extern __shared__ float sm[];
    float* As   = sm;
    float* ws   = As + 32 * 260;
    float* ts   = ws + 64 * 128;
    float* nw2s = ts + 32 * 132;

    const int tid = threadIdx.x;
    const int n0 = blockIdx.x * 32;
    const int tx = tid & 15, ny = tid >> 4;

    {
        int i = blockIdx.x * 256 + tid;
        if (i < N_NODES * 3)
            out[(size_t)N_NODES * H + i] = x[i] + g_xacc[i] * (1.f / (float)N_EDGES);
    }

    for (int i = tid; i < 128 * 128 / 4; i += 256)
        ((float4*)nw2s)[i] = ((const float4*)nw2)[i];
    for (int i = tid; i < 32 * 128 / 4; i += 256) {
        int fi = i * 4;
        int n = fi >> 7, c = fi & 127;
        *(float4*)&As[n * 260 + c]       = *(const float4*)&g_mi[(size_t)(n0 + n) * H + c];
        *(float4*)&As[n * 260 + 128 + c] = *(const float4*)&h[(size_t)(n0 + n) * H + c];
    }

    float acc[2][8];
    #pragma unroll
    for (int i = 0; i < 2; i++)
        #pragma unroll
        for (int j = 0; j < 8; j++)
            acc[i][j] = nb1[tx * 8 + j];

    for (int kt = 0; kt < 256; kt += 64) {
        __syncthreads();
        for (int i = tid; i < 64 * 128 / 4; i += 256)
            ((float4*)ws)[i] = ((const float4*)(nw1 + (size_t)kt * H))[i];
        __syncthreads();
        #pragma unroll 4
        for (int kk = 0; kk < 64; kk++) {
            float u0 = As[(2 * ny + 0) * 260 + kt + kk];
            float u1 = As[(2 * ny + 1) * 260 + kt + kk];
            float w[8];
            *(float4*)&w[0] = *(float4*)&ws[kk * 128 + tx * 8];
            *(float4*)&w[4] = *(float4*)&ws[kk * 128 + tx * 8 + 4];
            #pragma unroll
            for (int j = 0; j < 8; j++) { acc[0][j] += u0 * w[j]; acc[1][j] += u1 * w[j]; }
        }
    }
    #pragma unroll
    for (int i = 0; i < 2; i++) {
        float o[8];
        #pragma unroll
        for (int j = 0; j < 8; j++) o[j] = fmaxf(acc[i][j], 0.f);
        *(float4*)&ts[(2 * ny + i) * 132 + tx * 8]     = *(float4*)&o[0];
        *(float4*)&ts[(2 * ny + i) * 132 + tx * 8 + 4] = *(float4*)&o[4];
    }
    __syncthreads();

    float acc2[2][8];
    #pragma unroll
    for (int i = 0; i < 2; i++)
        #pragma unroll
        for (int j = 0; j < 8; j++)
            acc2[i][j] = nb2[tx * 8 + j];
    #pragma unroll 4
    for (int k = 0; k < 128; k++) {
        float u0 = ts[(2 * ny + 0) * 132 + k];
        float u1 = ts[(2 * ny + 1) * 132 + k];
        float w[8];
        *(float4*)&w[0] = *(float4*)&nw2s[k * 128 + tx * 8];
        *(float4*)&w[4] = *(float4*)&nw2s[k * 128 + tx * 8 + 4];
        #pragma unroll
        for (int j = 0; j < 8; j++) { acc2[0][j] += u0 * w[j]; acc2[1][j] += u1 * w[j]; }
    }
    #pragma unroll
    for (int i = 0; i < 2; i++) {
        *(float4*)&out[(size_t)(n0+2*ny+i)*H + tx*8]   = make_float4(acc2[i][0],acc2[i][1],acc2[i][2],acc2[i][3]);
        *(float4*)&out[(size_t)(n0+2*ny+i)*H + tx*8+4] = make_float4(acc2[i][4],acc2[i][5],acc2[i][6],acc2[i][7]);
    }
}

// =====================================================================
extern "C" void kernel_launch(void* const* d_in, const int* in_sizes, int n_in,
                              void* d_out, int out_size)
{
    const float* h    = (const float*)d_in[0];
    const float* x    = (const float*)d_in[1];
    const float* ea   = (const float*)d_in[2];
    const float* ew1  = (const float*)d_in[3];
    const float* eb1  = (const float*)d_in[4];
    const float* ew2  = (const float*)d_in[5];
    const float* eb2  = (const float*)d_in[6];
    const float* infw = (const float*)d_in[7];
    const float* infb = (const float*)d_in[8];
    const float* nw1  = (const float*)d_in[9];
    const float* nb1  = (const float*)d_in[10];
    const float* nw2  = (const float*)d_in[11];
    const float* nb2  = (const float*)d_in[12];
    const float* xw1  = (const float*)d_in[13];
    const float* xb1  = (const float*)d_in[14];
    const float* xw2  = (const float*)d_in[15];
    const float* xb2  = (const float*)d_in[16];
    const int*   ei   = (const int*)d_in[17];
    float* out = (float*)d_out;

    const int PRE_SMEM  = PRE_TOT * 4;     // 100864 bytes
    const int EDGE_SMEM = SM_TOT_E * 4;    // 159744 bytes
    const int POST_SMEM = 37120 * 4;
    cudaFuncSetAttribute(k_pre,  cudaFuncAttributeMaxDynamicSharedMemorySize, PRE_SMEM);
    cudaFuncSetAttribute(k_edge, cudaFuncAttributeMaxDynamicSharedMemorySize, EDGE_SMEM);
    cudaFuncSetAttribute(k_post, cudaFuncAttributeMaxDynamicSharedMemorySize, POST_SMEM);

    k_pre<<<PRE_GRID, 256, PRE_SMEM>>>(h, ew1, eb1);
    k_edge<<<148, 512, EDGE_SMEM>>>(x, ea, ew1, ew2, eb2, infw, infb,
                                    xw1, xb1, xw2, xb2, ei);
    k_post<<<625, 256, POST_SMEM>>>(h, x, nw1, nb1, nw2, nb2, out);
}